// round 7
// baseline (speedup 1.0000x reference)
#include <cuda_runtime.h>
#include <cuda_fp16.h>
#include <cstdint>
#include <math.h>

#define B_ROWS 16384
#define DDIM   512
#define EEXP   16
#define HDIM   256
#define LOUT   64

// ---------------- device scratch (allocation-free rule) ----------------
__device__ float  g_gates[B_ROWS * EEXP];
__device__ __half g_Xh [B_ROWS * DDIM];        // x, fp16
__device__ __half g_W1T[EEXP * HDIM * DDIM];   // [E][H][D], fp16
__device__ __half g_W2T[EEXP * LOUT * HDIM];   // [E][L][H], fp16

// ---------------- helpers ----------------
__device__ __forceinline__ uint32_t smem_u32_of(const void* p) {
    uint32_t a;
    asm("{ .reg .u64 t; cvta.to.shared.u64 t, %1; cvt.u32.u64 %0, t; }" : "=r"(a) : "l"(p));
    return a;
}
__device__ __forceinline__ float tanh_fast(float x) {
    float e = __expf(2.f * x);
    return 1.f - __fdividef(2.f, e + 1.f);
}
__device__ __forceinline__ float softplusf(float z) {
    return (z > 0.f) ? (z + log1pf(expf(-z))) : log1pf(expf(z));
}
__device__ __forceinline__ void cp16(uint32_t dst, const void* src) {
    asm volatile("cp.async.ca.shared.global [%0], [%1], 16;" :: "r"(dst), "l"(src));
}
#define CP_COMMIT() asm volatile("cp.async.commit_group;" ::: "memory")
#define CP_WAIT(n)  asm volatile("cp.async.wait_group %0;" :: "n"(n) : "memory")

#define LDMX4(r0, r1, r2, r3, addr) \
    asm volatile("ldmatrix.sync.aligned.m8n8.x4.shared.b16 {%0,%1,%2,%3}, [%4];" \
                 : "=r"(r0), "=r"(r1), "=r"(r2), "=r"(r3) : "r"(addr))

__device__ __forceinline__ void mma_f16(float* c, const uint32_t* a, const uint32_t* b) {
    asm volatile(
        "mma.sync.aligned.m16n8k16.row.col.f32.f16.f16.f32 "
        "{%0,%1,%2,%3}, {%4,%5,%6,%7}, {%8,%9}, {%0,%1,%2,%3};"
        : "+f"(c[0]), "+f"(c[1]), "+f"(c[2]), "+f"(c[3])
        : "r"(a[0]), "r"(a[1]), "r"(a[2]), "r"(a[3]), "r"(b[0]), "r"(b[1]));
}
__device__ __forceinline__ uint32_t pack_h2(float lo, float hi) {
    __half2 h = __floats2half2_rn(lo, hi);
    return *(uint32_t*)&h;
}

// ---------------------------------------------------------------------------
// x -> fp16
// ---------------------------------------------------------------------------
__global__ __launch_bounds__(256) void convx_kernel(const float4* __restrict__ in,
                                                    __half2* __restrict__ outv)
{
    int i = blockIdx.x * 256 + threadIdx.x;
    float4 v = in[i];
    outv[2 * i]     = __floats2half2_rn(v.x, v.y);
    outv[2 * i + 1] = __floats2half2_rn(v.z, v.w);
}

// ---------------------------------------------------------------------------
// Transpose + fp16: dst[e][c][r] = half(src[e][r][c])
// ---------------------------------------------------------------------------
__global__ void transposeh_kernel(const float* __restrict__ src, __half* __restrict__ dst,
                                  int R, int C)
{
    __shared__ float t[32][33];
    int e = blockIdx.z;
    const float* s = src + (size_t)e * R * C;
    __half* d = dst + (size_t)e * R * C;
    int c0 = blockIdx.x * 32, r0 = blockIdx.y * 32;
    int tx = threadIdx.x, ty = threadIdx.y;
    #pragma unroll
    for (int i = 0; i < 32; i += 8)
        t[ty + i][tx] = s[(size_t)(r0 + ty + i) * C + c0 + tx];
    __syncthreads();
    #pragma unroll
    for (int i = 0; i < 32; i += 8)
        d[(size_t)(c0 + ty + i) * R + r0 + tx] = __float2half_rn(t[tx][ty + i]);
}

// ---------------------------------------------------------------------------
// Gating v2: weights transposed in SMEM [32][516]; per-lane vectorized dot.
// GW_STRIDE = 516: multiple of 4 (float4-aligned rows); 516 mod 32 = 4, so an
// 8-lane LDS.128 phase hits 8 distinct bank-quads (conflict-free).
// ---------------------------------------------------------------------------
#define GW_STRIDE 516
#define G_WT   0                              // 32*516*4 = 66048
#define G_X    66048                          // 8 warps * 2 bufs * 512 f = 32768
#define G_SMEM 98816

__global__ __launch_bounds__(256) void gating_kernel(
    const float* __restrict__ x, const float* __restrict__ noise,
    const float* __restrict__ wg, const float* __restrict__ wn)
{
    extern __shared__ char gsm[];
    float* sWT = (float*)(gsm + G_WT);

    const int tid  = threadIdx.x;
    const int wid  = tid >> 5;
    const int lane = tid & 31;
    const int b0   = blockIdx.x * 64;

    // load transposed weights: sWT[j][d] = wg[d*16+j], sWT[16+j][d] = wn[d*16+j]
    for (int idx = tid; idx < 8192; idx += 256) {
        int d = idx >> 4, j = idx & 15;
        sWT[j * GW_STRIDE + d]        = wg[idx];
        sWT[(16 + j) * GW_STRIDE + d] = wn[idx];
    }
    __syncthreads();

    const uint32_t smem_b = smem_u32_of(gsm);
    const uint32_t xBase  = smem_b + G_X + wid * 4096;   // 2 bufs * 2048B

    auto stage_row = [&](int r, int buf) {
        const float* src = x + (size_t)r * DDIM;
        uint32_t dst = xBase + buf * 2048;
        #pragma unroll
        for (int q = 0; q < 4; q++)
            cp16(dst + (uint32_t)(q * 32 + lane) * 16, src + (q * 32 + lane) * 4);
        CP_COMMIT();
    };

    const float* wrow = sWT + lane * GW_STRIDE;

    int r0 = b0 + wid * 8;
    stage_row(r0, 0);

    for (int p = 0; p < 8; p++) {
        int r = r0 + p;
        int buf = p & 1;
        if (p + 1 < 8) stage_row(r + 1, buf ^ 1);
        if (p + 1 < 8) { CP_WAIT(1); } else { CP_WAIT(0); }
        __syncwarp();

        const float* xrow = (const float*)(gsm + G_X + wid * 4096 + buf * 2048);
        float acc = 0.f;
        #pragma unroll 4
        for (int d = 0; d < DDIM; d += 4) {
            float4 xv = *(const float4*)(xrow + d);       // broadcast
            float4 wv = *(const float4*)(wrow + d);       // conflict-free
            acc = fmaf(xv.x, wv.x, acc);
            acc = fmaf(xv.y, wv.y, acc);
            acc = fmaf(xv.z, wv.z, acc);
            acc = fmaf(xv.w, wv.w, acc);
        }
        __syncwarp();

        // lanes 0..15: clean logits; lanes 16..31: noise pre-activation
        float accN = __shfl_down_sync(0xffffffffu, acc, 16);
        float logit = 0.f;
        if (lane < 16) {
            float stddev = softplusf(accN) + 0.01f;
            logit = fmaf(noise[(size_t)r * EEXP + lane], stddev, acc);
        }
        // 16-lane softmax / threshold / renorm (lanes 0..15)
        float m = logit;
        #pragma unroll
        for (int o = 8; o; o >>= 1) m = fmaxf(m, __shfl_xor_sync(0xffffffffu, m, o, 16));
        float pr = expf(logit - m);
        float s = pr;
        #pragma unroll
        for (int o = 8; o; o >>= 1) s += __shfl_xor_sync(0xffffffffu, s, o, 16);
        float prob = pr / s;
        float s2 = prob;
        #pragma unroll
        for (int o = 8; o; o >>= 1) s2 += __shfl_xor_sync(0xffffffffu, s2, o, 16);
        float meanw = s2 * (1.f / 16.f) - 1e-8f;
        float gv = (prob >= meanw) ? prob : 0.f;
        float gs = gv;
        #pragma unroll
        for (int o = 8; o; o >>= 1) gs += __shfl_xor_sync(0xffffffffu, gs, o, 16);

        if (lane < 16)
            g_gates[(size_t)r * EEXP + lane] = gv / gs;
    }
}

// ---------------------------------------------------------------------------
// Fused expert MLP v3: fp16 mma + register-direct phase 2.
// CTA = (128 rows, expert e), 512 threads / 16 warps (4x4).
// Phase 1: C1[128,256] = x @ W1[e]  (warp tile 32x64, KC=32 double-buffered).
// tanh(C1+b1) converted IN REGISTERS to phase-2 A fragments (k-slice = warp's
// 64 h-columns). Phase 2: each warp computes partial C2[32,64] over its
// k-slice; 4 k-slice warps reduced via SMEM (two n-halves of 32).
// ---------------------------------------------------------------------------
#define SM_A0    0              // 128*40*2 = 10240
#define SM_A1    10240
#define SM_B0    20480          // 256*40*2 = 20480
#define SM_B1    40960
#define SM_W2    61440          // 64*264*2 = 33792
#define SM_RED   95232          // 4*128*32*4 = 65536
#define SM_BIAS  160768         // 256f + 64f = 1280
#define SMEM_MOE 162048

#define LDK1 40   // phase-1 tile stride (halves)
#define LDW2 264  // W2 tile stride (halves)

__global__ __launch_bounds__(512, 1) void moe_kernel(
    const float* __restrict__ b1, const float* __restrict__ b2,
    float* __restrict__ out)
{
    extern __shared__ char smem[];
    float* sRed   = (float*)(smem + SM_RED);
    float* sBias1 = (float*)(smem + SM_BIAS);
    float* sBias2 = sBias1 + HDIM;

    const int tid  = threadIdx.x;
    const int wid  = tid >> 5;
    const int lane = tid & 31;
    const int g    = lane >> 2;
    const int tig  = lane & 3;
    const int e    = blockIdx.y;
    const int m0   = blockIdx.x * 128;

    const uint32_t smem_b = smem_u32_of(smem);

    const __half* xg  = g_Xh  + (size_t)m0 * DDIM;
    const __half* w1e = g_W1T + (size_t)e * HDIM * DDIM;
    const __half* w2e = g_W2T + (size_t)e * LOUT * HDIM;

    if (tid < HDIM) sBias1[tid] = b1[(size_t)e * HDIM + tid];
    if (tid < LOUT) sBias2[tid] = b2[(size_t)e * LOUT + tid];

    // ldmatrix lane byte offsets
    const uint32_t offA  = (uint32_t)((lane & 15) * (LDK1 * 2) + (lane >> 4) * 16);
    const uint32_t offB  = (uint32_t)(((lane & 7) + ((lane >> 4) & 1) * 8) * (LDK1 * 2) + ((lane >> 3) & 1) * 16);
    const uint32_t offB2 = (uint32_t)(((lane & 7) + ((lane >> 4) & 1) * 8) * (LDW2 * 2) + ((lane >> 3) & 1) * 16);

    // ---------------- phase 1: 4x4 warp grid, 32x64 warp tiles ----------------
    const int wm = wid >> 2;      // row group (32 rows)
    const int wn = wid & 3;       // col group (64 cols) == phase-2 k-slice

    float acc[2][8][4];
    #pragma unroll
    for (int i = 0; i < 2; i++)
        #pragma unroll
        for (int j = 0; j < 8; j++)
            #pragma unroll
            for (int q = 0; q < 4; q++) acc[i][j][q] = 0.f;

    auto load_chunk1 = [&](int c, int buf) {
        uint32_t aBase = smem_b + (buf ? SM_A1 : SM_A0);
        uint32_t bBase = smem_b + (buf ? SM_B1 : SM_B0);
        {   // A: 128 rows x 32 halves = 512 cp16
            int r = tid >> 2, q = tid & 3;
            cp16(aBase + (uint32_t)(r * (LDK1 * 2) + q * 16),
                 xg + (size_t)r * DDIM + c * 32 + q * 8);
        }
        #pragma unroll
        for (int t = 0; t < 2; t++) {   // B: 256 rows x 32 halves = 1024 cp16
            int id = tid + t * 512;
            int r = id >> 2, q = id & 3;
            cp16(bBase + (uint32_t)(r * (LDK1 * 2) + q * 16),
                 w1e + (size_t)r * DDIM + c * 32 + q * 8);
        }
        CP_COMMIT();
    };

    load_chunk1(0, 0);

    for (int c = 0; c < 16; c++) {
        int buf = c & 1;
        if (c + 1 < 16) load_chunk1(c + 1, buf ^ 1);
        if (c + 1 < 16) { CP_WAIT(1); } else { CP_WAIT(0); }
        __syncthreads();

        const uint32_t aB = smem_b + (buf ? SM_A1 : SM_A0);
        const uint32_t bB = smem_b + (buf ? SM_B1 : SM_B0);

        #pragma unroll
        for (int ks = 0; ks < 32; ks += 16) {
            uint32_t af[2][4];
            #pragma unroll
            for (int i = 0; i < 2; i++) {
                uint32_t ad = aB + (uint32_t)(((wm * 32 + i * 16) * LDK1 + ks) * 2) + offA;
                LDMX4(af[i][0], af[i][1], af[i][2], af[i][3], ad);
            }
            uint32_t bf[8][2];
            #pragma unroll
            for (int j2 = 0; j2 < 4; j2++) {
                uint32_t bd = bB + (uint32_t)(((wn * 64 + j2 * 16) * LDK1 + ks) * 2) + offB;
                LDMX4(bf[2 * j2][0], bf[2 * j2][1], bf[2 * j2 + 1][0], bf[2 * j2 + 1][1], bd);
            }
            #pragma unroll
            for (int i = 0; i < 2; i++)
                #pragma unroll
                for (int j = 0; j < 8; j++)
                    mma_f16(acc[i][j], af[i], bf[j]);
        }
        __syncthreads();
    }

    // ---- load W2 tile [64][256] (single shot, own region) ----
    {
        uint32_t wBase = smem_b + SM_W2;
        #pragma unroll
        for (int t = 0; t < 4; t++) {    // 64 rows x 32 q x 16B
            int id = tid + t * 512;
            int r = id >> 5, q = id & 31;
            cp16(wBase + (uint32_t)(r * (LDW2 * 2) + q * 16),
                 w2e + (size_t)r * HDIM + q * 8);
        }
        CP_COMMIT();
    }

    // ---- tanh(C1 + b1) -> phase-2 A fragments IN REGISTERS ----
    uint32_t aFrag[2][4][4];
    #pragma unroll
    for (int i = 0; i < 2; i++) {
        #pragma unroll
        for (int jj = 0; jj < 4; jj++) {
            int c0 = wn * 64 + (2 * jj) * 8 + 2 * tig;
            int c1 = c0 + 8;
            float b00 = sBias1[c0], b01 = sBias1[c0 + 1];
            float b10 = sBias1[c1], b11 = sBias1[c1 + 1];
            aFrag[i][jj][0] = pack_h2(tanh_fast(acc[i][2*jj][0]   + b00), tanh_fast(acc[i][2*jj][1]   + b01));
            aFrag[i][jj][1] = pack_h2(tanh_fast(acc[i][2*jj][2]   + b00), tanh_fast(acc[i][2*jj][3]   + b01));
            aFrag[i][jj][2] = pack_h2(tanh_fast(acc[i][2*jj+1][0] + b10), tanh_fast(acc[i][2*jj+1][1] + b11));
            aFrag[i][jj][3] = pack_h2(tanh_fast(acc[i][2*jj+1][2] + b10), tanh_fast(acc[i][2*jj+1][3] + b11));
        }
    }

    CP_WAIT(0);
    __syncthreads();   // W2 visible to all warps

    const uint32_t wB = smem_b + SM_W2;

    // ---------------- phase 2: two n-halves of 32 ----------------
    #pragma unroll
    for (int nh = 0; nh < 2; nh++) {
        if (nh == 1) __syncthreads();    // protect sRed reuse

        float acc2[2][4][4];
        #pragma unroll
        for (int i = 0; i < 2; i++)
            #pragma unroll
            for (int nb = 0; nb < 4; nb++)
                #pragma unroll
                for (int q = 0; q < 4; q++) acc2[i][nb][q] = 0.f;

        #pragma unroll
        for (int jj = 0; jj < 4; jj++) {
            int kg = wn * 64 + jj * 16;
            #pragma unroll
            for (int nb2 = 0; nb2 < 2; nb2++) {
                uint32_t bf[4];
                uint32_t bd = wB + (uint32_t)(((nh * 32 + nb2 * 16) * LDW2 + kg) * 2) + offB2;
                LDMX4(bf[0], bf[1], bf[2], bf[3], bd);
                #pragma unroll
                for (int i = 0; i < 2; i++) {
                    mma_f16(acc2[i][2*nb2],     aFrag[i][jj], bf);
                    mma_f16(acc2[i][2*nb2 + 1], aFrag[i][jj], bf + 2);
                }
            }
        }

        // store partials: sRed[wn][row 0..127][col 0..31]
        float* base = sRed + wn * (128 * 32);
        #pragma unroll
        for (int i = 0; i < 2; i++) {
            int rA = wm * 32 + i * 16 + g;
            #pragma unroll
            for (int nb = 0; nb < 4; nb++) {
                int cc = nb * 8 + 2 * tig;
                *(float2*)&base[rA * 32 + cc]       = make_float2(acc2[i][nb][0], acc2[i][nb][1]);
                *(float2*)&base[(rA + 8) * 32 + cc] = make_float2(acc2[i][nb][2], acc2[i][nb][3]);
            }
        }
        __syncthreads();

        // reduce 4 partials + bias + gate -> out
        #pragma unroll
        for (int t = 0; t < 2; t++) {
            int idx = tid + t * 512;          // 0..1023 float4 slots
            int row = idx >> 3, c4 = (idx & 7) * 4;
            float4 v0 = *(float4*)&sRed[0 * 4096 + row * 32 + c4];
            float4 v1 = *(float4*)&sRed[1 * 4096 + row * 32 + c4];
            float4 v2 = *(float4*)&sRed[2 * 4096 + row * 32 + c4];
            float4 v3 = *(float4*)&sRed[3 * 4096 + row * 32 + c4];
            int lc = nh * 32 + c4;
            float gate = g_gates[(size_t)(m0 + row) * EEXP + e];
            float4 o;
            o.x = (v0.x + v1.x + v2.x + v3.x + sBias2[lc + 0]) * gate;
            o.y = (v0.y + v1.y + v2.y + v3.y + sBias2[lc + 1]) * gate;
            o.z = (v0.z + v1.z + v2.z + v3.z + sBias2[lc + 2]) * gate;
            o.w = (v0.w + v1.w + v2.w + v3.w + sBias2[lc + 3]) * gate;
            *(float4*)(out + ((size_t)(m0 + row) * EEXP + e) * LOUT + lc) = o;
        }
    }
}

// ---------------------------------------------------------------------------
extern "C" void kernel_launch(void* const* d_in, const int* in_sizes, int n_in,
                              void* d_out, int out_size)
{
    const float* x       = (const float*)d_in[0];
    const float* noise   = (const float*)d_in[1];
    const float* w_gate  = (const float*)d_in[2];
    const float* w_noise = (const float*)d_in[3];
    const float* W1      = (const float*)d_in[4];
    const float* b1      = (const float*)d_in[5];
    const float* W2      = (const float*)d_in[6];
    const float* b2      = (const float*)d_in[7];
    float* out = (float*)d_out;

    __half* xh;  cudaGetSymbolAddress((void**)&xh,  g_Xh);
    __half* w1t; cudaGetSymbolAddress((void**)&w1t, g_W1T);
    __half* w2t; cudaGetSymbolAddress((void**)&w2t, g_W2T);

    cudaFuncSetAttribute(gating_kernel, cudaFuncAttributeMaxDynamicSharedMemorySize, G_SMEM);
    cudaFuncSetAttribute(moe_kernel,    cudaFuncAttributeMaxDynamicSharedMemorySize, SMEM_MOE);

    convx_kernel<<<B_ROWS * DDIM / 4 / 256, 256>>>((const float4*)x, (__half2*)xh);
    transposeh_kernel<<<dim3(HDIM / 32, DDIM / 32, EEXP), dim3(32, 8)>>>(W1, w1t, DDIM, HDIM);
    transposeh_kernel<<<dim3(LOUT / 32, HDIM / 32, EEXP), dim3(32, 8)>>>(W2, w2t, HDIM, LOUT);
    gating_kernel<<<B_ROWS / 64, 256, G_SMEM>>>(x, noise, w_gate, w_noise);
    moe_kernel<<<dim3(B_ROWS / 128, EEXP), 512, SMEM_MOE>>>(b1, b2, out);
}

// round 8
// speedup vs baseline: 1.0335x; 1.0335x over previous
#include <cuda_runtime.h>
#include <cuda_fp16.h>
#include <cstdint>
#include <math.h>

#define B_ROWS 16384
#define DDIM   512
#define EEXP   16
#define HDIM   256
#define LOUT   64

// ---------------- device scratch (allocation-free rule) ----------------
__device__ float  g_gates[B_ROWS * EEXP];
__device__ __half g_Xh [B_ROWS * DDIM];        // x, fp16
__device__ __half g_W1T[EEXP * HDIM * DDIM];   // [E][H][D], fp16
__device__ __half g_W2T[EEXP * LOUT * HDIM];   // [E][L][H], fp16

// ---------------- helpers ----------------
__device__ __forceinline__ uint32_t smem_u32_of(const void* p) {
    uint32_t a;
    asm("{ .reg .u64 t; cvta.to.shared.u64 t, %1; cvt.u32.u64 %0, t; }" : "=r"(a) : "l"(p));
    return a;
}
__device__ __forceinline__ float tanh_fast(float x) {
    float e = __expf(2.f * x);
    return 1.f - __fdividef(2.f, e + 1.f);
}
__device__ __forceinline__ float softplusf(float z) {
    return (z > 0.f) ? (z + log1pf(expf(-z))) : log1pf(expf(z));
}
__device__ __forceinline__ void cp16(uint32_t dst, const void* src) {
    asm volatile("cp.async.ca.shared.global [%0], [%1], 16;" :: "r"(dst), "l"(src));
}
#define CP_COMMIT() asm volatile("cp.async.commit_group;" ::: "memory")
#define CP_WAIT(n)  asm volatile("cp.async.wait_group %0;" :: "n"(n) : "memory")

#define LDMX4(r0, r1, r2, r3, addr) \
    asm volatile("ldmatrix.sync.aligned.m8n8.x4.shared.b16 {%0,%1,%2,%3}, [%4];" \
                 : "=r"(r0), "=r"(r1), "=r"(r2), "=r"(r3) : "r"(addr))

__device__ __forceinline__ void mma_f16(float* c, const uint32_t* a, const uint32_t* b) {
    asm volatile(
        "mma.sync.aligned.m16n8k16.row.col.f32.f16.f16.f32 "
        "{%0,%1,%2,%3}, {%4,%5,%6,%7}, {%8,%9}, {%0,%1,%2,%3};"
        : "+f"(c[0]), "+f"(c[1]), "+f"(c[2]), "+f"(c[3])
        : "r"(a[0]), "r"(a[1]), "r"(a[2]), "r"(a[3]), "r"(b[0]), "r"(b[1]));
}

// ---------------------------------------------------------------------------
// x -> fp16
// ---------------------------------------------------------------------------
__global__ __launch_bounds__(256) void convx_kernel(const float4* __restrict__ in,
                                                    __half2* __restrict__ outv)
{
    int i = blockIdx.x * 256 + threadIdx.x;
    float4 v = in[i];
    outv[2 * i]     = __floats2half2_rn(v.x, v.y);
    outv[2 * i + 1] = __floats2half2_rn(v.z, v.w);
}

// ---------------------------------------------------------------------------
// Transpose + fp16: dst[e][c][r] = half(src[e][r][c])
// ---------------------------------------------------------------------------
__global__ void transposeh_kernel(const float* __restrict__ src, __half* __restrict__ dst,
                                  int R, int C)
{
    __shared__ float t[32][33];
    int e = blockIdx.z;
    const float* s = src + (size_t)e * R * C;
    __half* d = dst + (size_t)e * R * C;
    int c0 = blockIdx.x * 32, r0 = blockIdx.y * 32;
    int tx = threadIdx.x, ty = threadIdx.y;
    #pragma unroll
    for (int i = 0; i < 32; i += 8)
        t[ty + i][tx] = s[(size_t)(r0 + ty + i) * C + c0 + tx];
    __syncthreads();
    #pragma unroll
    for (int i = 0; i < 32; i += 8)
        d[(size_t)(c0 + ty + i) * R + r0 + tx] = __float2half_rn(t[tx][ty + i]);
}

// ---------------------------------------------------------------------------
// Gating v3: one warp per row, 4 independent FMA chains per lane.
// Weights transposed in SMEM [32][516]; x row via lane-uniform LDG (broadcast).
// ---------------------------------------------------------------------------
#define GW_STRIDE 516
#define G_SMEM (32 * GW_STRIDE * 4)   // 66048

__global__ __launch_bounds__(512) void gating_kernel(
    const float* __restrict__ x, const float* __restrict__ noise,
    const float* __restrict__ wg, const float* __restrict__ wn)
{
    extern __shared__ float sWT[];

    const int tid  = threadIdx.x;
    const int wid  = tid >> 5;
    const int lane = tid & 31;
    const int b0   = blockIdx.x * 64;

    // transposed weights: sWT[j][d] = wg[d*16+j], sWT[16+j][d] = wn[d*16+j]
    for (int idx = tid; idx < 8192; idx += 512) {
        int d = idx >> 4, j = idx & 15;
        sWT[j * GW_STRIDE + d]        = wg[idx];
        sWT[(16 + j) * GW_STRIDE + d] = wn[idx];
    }
    __syncthreads();

    const float* wrow = sWT + lane * GW_STRIDE;

    #pragma unroll
    for (int p = 0; p < 4; p++) {
        int r = b0 + p * 16 + wid;
        const float4* xr4 = (const float4*)(x + (size_t)r * DDIM);

        float a0 = 0.f, a1 = 0.f, a2 = 0.f, a3 = 0.f;
        #pragma unroll 8
        for (int q = 0; q < 128; q += 4) {
            float4 x0 = __ldg(xr4 + q);
            float4 x1 = __ldg(xr4 + q + 1);
            float4 x2 = __ldg(xr4 + q + 2);
            float4 x3 = __ldg(xr4 + q + 3);
            float4 w0 = *(const float4*)(wrow + q * 4);
            float4 w1 = *(const float4*)(wrow + q * 4 + 4);
            float4 w2 = *(const float4*)(wrow + q * 4 + 8);
            float4 w3 = *(const float4*)(wrow + q * 4 + 12);
            a0 = fmaf(x0.x, w0.x, a0); a0 = fmaf(x0.y, w0.y, a0);
            a0 = fmaf(x0.z, w0.z, a0); a0 = fmaf(x0.w, w0.w, a0);
            a1 = fmaf(x1.x, w1.x, a1); a1 = fmaf(x1.y, w1.y, a1);
            a1 = fmaf(x1.z, w1.z, a1); a1 = fmaf(x1.w, w1.w, a1);
            a2 = fmaf(x2.x, w2.x, a2); a2 = fmaf(x2.y, w2.y, a2);
            a2 = fmaf(x2.z, w2.z, a2); a2 = fmaf(x2.w, w2.w, a2);
            a3 = fmaf(x3.x, w3.x, a3); a3 = fmaf(x3.y, w3.y, a3);
            a3 = fmaf(x3.z, w3.z, a3); a3 = fmaf(x3.w, w3.w, a3);
        }
        float acc = (a0 + a1) + (a2 + a3);

        // lanes 0..15: clean logits; lanes 16..31: noise pre-activation
        float accN = __shfl_down_sync(0xffffffffu, acc, 16);
        float logit = 0.f;
        if (lane < 16) {
            float stddev = softplusf(accN) + 0.01f;
            logit = fmaf(noise[(size_t)r * EEXP + lane], stddev, acc);
        }
        float m = logit;
        #pragma unroll
        for (int o = 8; o; o >>= 1) m = fmaxf(m, __shfl_xor_sync(0xffffffffu, m, o, 16));
        float pr = expf(logit - m);
        float s = pr;
        #pragma unroll
        for (int o = 8; o; o >>= 1) s += __shfl_xor_sync(0xffffffffu, s, o, 16);
        float prob = pr / s;
        float s2 = prob;
        #pragma unroll
        for (int o = 8; o; o >>= 1) s2 += __shfl_xor_sync(0xffffffffu, s2, o, 16);
        float meanw = s2 * (1.f / 16.f) - 1e-8f;
        float gv = (prob >= meanw) ? prob : 0.f;
        float gs = gv;
        #pragma unroll
        for (int o = 8; o; o >>= 1) gs += __shfl_xor_sync(0xffffffffu, gs, o, 16);

        if (lane < 16)
            g_gates[(size_t)r * EEXP + lane] = gv / gs;
    }
}

// ---------------------------------------------------------------------------
// Fused expert MLP v5 (R5 structure + single-sync mainloop + resident W2).
// CTA = (128 rows, expert e), 512 threads / 16 warps (4x4).
// Phase 1: C1[128,256] = x @ W1[e] (warp tile 32x64, KC=32 double-buffered,
//          ONE barrier per chunk). h = tanh(C1+b1) -> sH fp16 [128][264].
// Phase 2: barrier-free; W2 resident [64][264]; warp tile 32x16, full K=256.
// ---------------------------------------------------------------------------
#define SM_H     0              // 128*264*2 = 67584
#define SM_A0    67584          // 128*40*2  = 10240
#define SM_A1    77824
#define SM_B0    88064          // 256*40*2  = 20480
#define SM_B1    108544
#define SM_W2    129024         // 64*264*2  = 33792
#define SM_BIAS  162816         // 256f + 64f = 1280
#define SMEM_MOE 164096

#define LDK1 40   // phase-1 tile stride (halves)
#define LDH  264  // h tile stride (halves)
#define LDW2 264  // W2 tile stride (halves)

__global__ __launch_bounds__(512, 1) void moe_kernel(
    const float* __restrict__ b1, const float* __restrict__ b2,
    float* __restrict__ out)
{
    extern __shared__ char smem[];
    __half* sH    = (__half*)(smem + SM_H);
    float* sBias1 = (float*)(smem + SM_BIAS);
    float* sBias2 = sBias1 + HDIM;

    const int tid  = threadIdx.x;
    const int wid  = tid >> 5;
    const int lane = tid & 31;
    const int g    = lane >> 2;
    const int tig  = lane & 3;
    const int e    = blockIdx.y;
    const int m0   = blockIdx.x * 128;

    const uint32_t smem_b = smem_u32_of(smem);

    const __half* xg  = g_Xh  + (size_t)m0 * DDIM;
    const __half* w1e = g_W1T + (size_t)e * HDIM * DDIM;
    const __half* w2e = g_W2T + (size_t)e * LOUT * HDIM;

    if (tid < HDIM) sBias1[tid] = b1[(size_t)e * HDIM + tid];
    if (tid < LOUT) sBias2[tid] = b2[(size_t)e * LOUT + tid];

    // ldmatrix lane byte offsets
    const uint32_t offA  = (uint32_t)((lane & 15) * (LDK1 * 2) + (lane >> 4) * 16);
    const uint32_t offB  = (uint32_t)(((lane & 7) + ((lane >> 4) & 1) * 8) * (LDK1 * 2) + ((lane >> 3) & 1) * 16);
    const uint32_t offA2 = (uint32_t)((lane & 15) * (LDH * 2) + (lane >> 4) * 16);
    const uint32_t offB2 = (uint32_t)(((lane & 7) + ((lane >> 4) & 1) * 8) * (LDW2 * 2) + ((lane >> 3) & 1) * 16);

    // ---------------- phase 1: 4x4 warp grid, 32x64 warp tiles ----------------
    const int wm = wid >> 2;
    const int wn = wid & 3;

    float acc[2][8][4];
    #pragma unroll
    for (int i = 0; i < 2; i++)
        #pragma unroll
        for (int j = 0; j < 8; j++)
            #pragma unroll
            for (int q = 0; q < 4; q++) acc[i][j][q] = 0.f;

    auto load_chunk1 = [&](int c, int buf) {
        uint32_t aBase = smem_b + (buf ? SM_A1 : SM_A0);
        uint32_t bBase = smem_b + (buf ? SM_B1 : SM_B0);
        {   // A: 128 rows x 32 halves
            int r = tid >> 2, q = tid & 3;
            cp16(aBase + (uint32_t)(r * (LDK1 * 2) + q * 16),
                 xg + (size_t)r * DDIM + c * 32 + q * 8);
        }
        #pragma unroll
        for (int t = 0; t < 2; t++) {   // B: 256 rows x 32 halves
            int id = tid + t * 512;
            int r = id >> 2, q = id & 3;
            cp16(bBase + (uint32_t)(r * (LDK1 * 2) + q * 16),
                 w1e + (size_t)r * DDIM + c * 32 + q * 8);
        }
        CP_COMMIT();
    };

    load_chunk1(0, 0);

    for (int c = 0; c < 16; c++) {
        int buf = c & 1;
        CP_WAIT(0);            // chunk c landed (single pending group)
        __syncthreads();       // prior reads of buf^1 are done (one barrier/iter)
        if (c + 1 < 16) {
            load_chunk1(c + 1, buf ^ 1);
        } else {
            // last iteration: single-shot W2 [64][256] -> resident region
            uint32_t wBase = smem_b + SM_W2;
            #pragma unroll
            for (int t = 0; t < 4; t++) {
                int id = tid + t * 512;
                int r = id >> 5, q = id & 31;
                cp16(wBase + (uint32_t)(r * (LDW2 * 2) + q * 16),
                     w2e + (size_t)r * HDIM + q * 8);
            }
            CP_COMMIT();
        }

        const uint32_t aB = smem_b + (buf ? SM_A1 : SM_A0);
        const uint32_t bB = smem_b + (buf ? SM_B1 : SM_B0);

        #pragma unroll
        for (int ks = 0; ks < 32; ks += 16) {
            uint32_t af[2][4];
            #pragma unroll
            for (int i = 0; i < 2; i++) {
                uint32_t ad = aB + (uint32_t)(((wm * 32 + i * 16) * LDK1 + ks) * 2) + offA;
                LDMX4(af[i][0], af[i][1], af[i][2], af[i][3], ad);
            }
            uint32_t bf[8][2];
            #pragma unroll
            for (int j2 = 0; j2 < 4; j2++) {
                uint32_t bd = bB + (uint32_t)(((wn * 64 + j2 * 16) * LDK1 + ks) * 2) + offB;
                LDMX4(bf[2 * j2][0], bf[2 * j2][1], bf[2 * j2 + 1][0], bf[2 * j2 + 1][1], bd);
            }
            #pragma unroll
            for (int i = 0; i < 2; i++)
                #pragma unroll
                for (int j = 0; j < 8; j++)
                    mma_f16(acc[i][j], af[i], bf[j]);
        }
    }

    // ---- tanh(C1 + b1) -> sH (fp16), half2 stores ----
    #pragma unroll
    for (int i = 0; i < 2; i++) {
        int r0 = wm * 32 + i * 16 + g;
        #pragma unroll
        for (int j = 0; j < 8; j++) {
            int cc = wn * 64 + j * 8 + 2 * tig;
            float bb0 = sBias1[cc], bb1 = sBias1[cc + 1];
            *(__half2*)&sH[r0 * LDH + cc] =
                __floats2half2_rn(tanh_fast(acc[i][j][0] + bb0), tanh_fast(acc[i][j][1] + bb1));
            *(__half2*)&sH[(r0 + 8) * LDH + cc] =
                __floats2half2_rn(tanh_fast(acc[i][j][2] + bb0), tanh_fast(acc[i][j][3] + bb1));
        }
    }
    CP_WAIT(0);          // W2 resident
    __syncthreads();     // sH visible; phase 2 is barrier-free from here

    // ---------------- phase 2: 4x4 warp grid, 32x16 warp tiles, K=256 -------
    const int wm2 = wid >> 2;
    const int wn2 = wid & 3;

    float acc2[2][2][4];
    #pragma unroll
    for (int i = 0; i < 2; i++)
        #pragma unroll
        for (int j = 0; j < 2; j++)
            #pragma unroll
            for (int q = 0; q < 4; q++) acc2[i][j][q] = 0.f;

    const uint32_t hB = smem_b + SM_H;
    const uint32_t wB = smem_b + SM_W2;

    #pragma unroll
    for (int ks = 0; ks < 256; ks += 16) {
        uint32_t af[2][4];
        #pragma unroll
        for (int i = 0; i < 2; i++) {
            uint32_t ad = hB + (uint32_t)(((wm2 * 32 + i * 16) * LDH + ks) * 2) + offA2;
            LDMX4(af[i][0], af[i][1], af[i][2], af[i][3], ad);
        }
        uint32_t bf[4];
        uint32_t bd = wB + (uint32_t)(((wn2 * 16) * LDW2 + ks) * 2) + offB2;
        LDMX4(bf[0], bf[1], bf[2], bf[3], bd);
        #pragma unroll
        for (int i = 0; i < 2; i++) {
            mma_f16(acc2[i][0], af[i], bf);
            mma_f16(acc2[i][1], af[i], bf + 2);
        }
    }

    // ---- epilogue: out = gate * (C2 + b2) ----
    #pragma unroll
    for (int i = 0; i < 2; i++) {
        int r0 = wm2 * 32 + i * 16 + g;
        int mA = m0 + r0, mB = mA + 8;
        float gateA = g_gates[(size_t)mA * EEXP + e];
        float gateB = g_gates[(size_t)mB * EEXP + e];
        float* opA = out + ((size_t)mA * EEXP + e) * LOUT;
        float* opB = out + ((size_t)mB * EEXP + e) * LOUT;
        #pragma unroll
        for (int j = 0; j < 2; j++) {
            int cc = wn2 * 16 + j * 8 + 2 * tig;
            float bb0 = sBias2[cc], bb1 = sBias2[cc + 1];
            float2 oA, oB;
            oA.x = (acc2[i][j][0] + bb0) * gateA;
            oA.y = (acc2[i][j][1] + bb1) * gateA;
            oB.x = (acc2[i][j][2] + bb0) * gateB;
            oB.y = (acc2[i][j][3] + bb1) * gateB;
            *(float2*)(opA + cc) = oA;
            *(float2*)(opB + cc) = oB;
        }
    }
}

// ---------------------------------------------------------------------------
extern "C" void kernel_launch(void* const* d_in, const int* in_sizes, int n_in,
                              void* d_out, int out_size)
{
    const float* x       = (const float*)d_in[0];
    const float* noise   = (const float*)d_in[1];
    const float* w_gate  = (const float*)d_in[2];
    const float* w_noise = (const float*)d_in[3];
    const float* W1      = (const float*)d_in[4];
    const float* b1      = (const float*)d_in[5];
    const float* W2      = (const float*)d_in[6];
    const float* b2      = (const float*)d_in[7];
    float* out = (float*)d_out;

    __half* xh;  cudaGetSymbolAddress((void**)&xh,  g_Xh);
    __half* w1t; cudaGetSymbolAddress((void**)&w1t, g_W1T);
    __half* w2t; cudaGetSymbolAddress((void**)&w2t, g_W2T);

    cudaFuncSetAttribute(gating_kernel, cudaFuncAttributeMaxDynamicSharedMemorySize, G_SMEM);
    cudaFuncSetAttribute(moe_kernel,    cudaFuncAttributeMaxDynamicSharedMemorySize, SMEM_MOE);

    convx_kernel<<<B_ROWS * DDIM / 4 / 256, 256>>>((const float4*)x, (__half2*)xh);
    transposeh_kernel<<<dim3(HDIM / 32, DDIM / 32, EEXP), dim3(32, 8)>>>(W1, w1t, DDIM, HDIM);
    transposeh_kernel<<<dim3(LOUT / 32, HDIM / 32, EEXP), dim3(32, 8)>>>(W2, w2t, HDIM, LOUT);
    gating_kernel<<<B_ROWS / 64, 512, G_SMEM>>>(x, noise, w_gate, w_noise);
    moe_kernel<<<dim3(B_ROWS / 128, EEXP), 512, SMEM_MOE>>>(b1, b2, out);
}

// round 9
// speedup vs baseline: 1.1039x; 1.0682x over previous
#include <cuda_runtime.h>
#include <cuda_fp16.h>
#include <cstdint>
#include <math.h>

#define B_ROWS 16384
#define DDIM   512
#define EEXP   16
#define HDIM   256
#define LOUT   64

// ---------------- device scratch (allocation-free rule) ----------------
__device__ float  g_gates[B_ROWS * EEXP];
__device__ __half g_Xh [B_ROWS * DDIM];        // x, fp16
__device__ __half g_W1T[EEXP * HDIM * DDIM];   // [E][H][D], fp16
__device__ __half g_W2T[EEXP * LOUT * HDIM];   // [E][L][H], fp16

// ---------------- helpers ----------------
__device__ __forceinline__ uint32_t smem_u32_of(const void* p) {
    uint32_t a;
    asm("{ .reg .u64 t; cvta.to.shared.u64 t, %1; cvt.u32.u64 %0, t; }" : "=r"(a) : "l"(p));
    return a;
}
__device__ __forceinline__ float tanh_fast(float x) {
    float e = __expf(2.f * x);
    return 1.f - __fdividef(2.f, e + 1.f);
}
__device__ __forceinline__ float softplusf(float z) {
    return (z > 0.f) ? (z + log1pf(expf(-z))) : log1pf(expf(z));
}
__device__ __forceinline__ void cp16(uint32_t dst, const void* src) {
    asm volatile("cp.async.ca.shared.global [%0], [%1], 16;" :: "r"(dst), "l"(src));
}
#define CP_COMMIT() asm volatile("cp.async.commit_group;" ::: "memory")
#define CP_WAIT(n)  asm volatile("cp.async.wait_group %0;" :: "n"(n) : "memory")

#define LDMX4(r0, r1, r2, r3, addr) \
    asm volatile("ldmatrix.sync.aligned.m8n8.x4.shared.b16 {%0,%1,%2,%3}, [%4];" \
                 : "=r"(r0), "=r"(r1), "=r"(r2), "=r"(r3) : "r"(addr))

__device__ __forceinline__ void mma_f16(float* c, const uint32_t* a, const uint32_t* b) {
    asm volatile(
        "mma.sync.aligned.m16n8k16.row.col.f32.f16.f16.f32 "
        "{%0,%1,%2,%3}, {%4,%5,%6,%7}, {%8,%9}, {%0,%1,%2,%3};"
        : "+f"(c[0]), "+f"(c[1]), "+f"(c[2]), "+f"(c[3])
        : "r"(a[0]), "r"(a[1]), "r"(a[2]), "r"(a[3]), "r"(b[0]), "r"(b[1]));
}

// ---------------------------------------------------------------------------
// x -> fp16
// ---------------------------------------------------------------------------
__global__ __launch_bounds__(256) void convx_kernel(const float4* __restrict__ in,
                                                    __half2* __restrict__ outv)
{
    int i = blockIdx.x * 256 + threadIdx.x;
    float4 v = in[i];
    outv[2 * i]     = __floats2half2_rn(v.x, v.y);
    outv[2 * i + 1] = __floats2half2_rn(v.z, v.w);
}

// ---------------------------------------------------------------------------
// Transpose + fp16: dst[e][c][r] = half(src[e][r][c])
// ---------------------------------------------------------------------------
__global__ void transposeh_kernel(const float* __restrict__ src, __half* __restrict__ dst,
                                  int R, int C)
{
    __shared__ float t[32][33];
    int e = blockIdx.z;
    const float* s = src + (size_t)e * R * C;
    __half* d = dst + (size_t)e * R * C;
    int c0 = blockIdx.x * 32, r0 = blockIdx.y * 32;
    int tx = threadIdx.x, ty = threadIdx.y;
    #pragma unroll
    for (int i = 0; i < 32; i += 8)
        t[ty + i][tx] = s[(size_t)(r0 + ty + i) * C + c0 + tx];
    __syncthreads();
    #pragma unroll
    for (int i = 0; i < 32; i += 8)
        d[(size_t)(c0 + ty + i) * R + r0 + tx] = __float2half_rn(t[tx][ty + i]);
}

// ---------------------------------------------------------------------------
// Gating v4: ONE row per warp, 1024 CTAs x 16 warps (grid-limited occ fixed).
// Weights transposed in SMEM [32][516]; 4 independent FMA chains per lane.
// ---------------------------------------------------------------------------
#define GW_STRIDE 516
#define G_SMEM (32 * GW_STRIDE * 4)   // 66048

__global__ __launch_bounds__(512) void gating_kernel(
    const float* __restrict__ x, const float* __restrict__ noise,
    const float* __restrict__ wg, const float* __restrict__ wn)
{
    extern __shared__ float sWT[];

    const int tid  = threadIdx.x;
    const int wid  = tid >> 5;
    const int lane = tid & 31;

    // transposed weights: sWT[j][d] = wg[d*16+j], sWT[16+j][d] = wn[d*16+j]
    for (int idx = tid; idx < 8192; idx += 512) {
        int d = idx >> 4, j = idx & 15;
        sWT[j * GW_STRIDE + d]        = wg[idx];
        sWT[(16 + j) * GW_STRIDE + d] = wn[idx];
    }
    __syncthreads();

    const float* wrow = sWT + lane * GW_STRIDE;
    const int r = blockIdx.x * 16 + wid;
    const float4* xr4 = (const float4*)(x + (size_t)r * DDIM);

    float a0 = 0.f, a1 = 0.f, a2 = 0.f, a3 = 0.f;
    #pragma unroll 8
    for (int q = 0; q < 128; q += 4) {
        float4 x0 = __ldg(xr4 + q);
        float4 x1 = __ldg(xr4 + q + 1);
        float4 x2 = __ldg(xr4 + q + 2);
        float4 x3 = __ldg(xr4 + q + 3);
        float4 w0 = *(const float4*)(wrow + q * 4);
        float4 w1 = *(const float4*)(wrow + q * 4 + 4);
        float4 w2 = *(const float4*)(wrow + q * 4 + 8);
        float4 w3 = *(const float4*)(wrow + q * 4 + 12);
        a0 = fmaf(x0.x, w0.x, a0); a0 = fmaf(x0.y, w0.y, a0);
        a0 = fmaf(x0.z, w0.z, a0); a0 = fmaf(x0.w, w0.w, a0);
        a1 = fmaf(x1.x, w1.x, a1); a1 = fmaf(x1.y, w1.y, a1);
        a1 = fmaf(x1.z, w1.z, a1); a1 = fmaf(x1.w, w1.w, a1);
        a2 = fmaf(x2.x, w2.x, a2); a2 = fmaf(x2.y, w2.y, a2);
        a2 = fmaf(x2.z, w2.z, a2); a2 = fmaf(x2.w, w2.w, a2);
        a3 = fmaf(x3.x, w3.x, a3); a3 = fmaf(x3.y, w3.y, a3);
        a3 = fmaf(x3.z, w3.z, a3); a3 = fmaf(x3.w, w3.w, a3);
    }
    float acc = (a0 + a1) + (a2 + a3);

    // lanes 0..15: clean logits; lanes 16..31: noise pre-activation
    float accN = __shfl_down_sync(0xffffffffu, acc, 16);
    float logit = 0.f;
    if (lane < 16) {
        float stddev = softplusf(accN) + 0.01f;
        logit = fmaf(noise[(size_t)r * EEXP + lane], stddev, acc);
    }
    float m = logit;
    #pragma unroll
    for (int o = 8; o; o >>= 1) m = fmaxf(m, __shfl_xor_sync(0xffffffffu, m, o, 16));
    float pr = expf(logit - m);
    float s = pr;
    #pragma unroll
    for (int o = 8; o; o >>= 1) s += __shfl_xor_sync(0xffffffffu, s, o, 16);
    float prob = pr / s;
    float s2 = prob;
    #pragma unroll
    for (int o = 8; o; o >>= 1) s2 += __shfl_xor_sync(0xffffffffu, s2, o, 16);
    float meanw = s2 * (1.f / 16.f) - 1e-8f;
    float gv = (prob >= meanw) ? prob : 0.f;
    float gs = gv;
    #pragma unroll
    for (int o = 8; o; o >>= 1) gs += __shfl_xor_sync(0xffffffffu, gs, o, 16);

    if (lane < 16)
        g_gates[(size_t)r * EEXP + lane] = gv / gs;
}

// ---------------------------------------------------------------------------
// Fused expert MLP v6: v5 + 3-stage cp.async pipeline (2 chunks in flight).
// CTA = (128 rows, expert e), 512 threads / 16 warps (4x4).
// ---------------------------------------------------------------------------
#define SM_H     0              // 128*264*2 = 67584
#define SM_A0    67584          // 128*40*2  = 10240 (x3)
#define SM_B0    98304          // 256*40*2  = 20480 (x3)
#define SM_W2    159744         // 64*264*2  = 33792
#define SM_BIAS  193536         // 256f + 64f = 1280
#define SMEM_MOE 194816

#define LDK1 40   // phase-1 tile stride (halves)
#define LDH  264  // h tile stride (halves)
#define LDW2 264  // W2 tile stride (halves)

__global__ __launch_bounds__(512, 1) void moe_kernel(
    const float* __restrict__ b1, const float* __restrict__ b2,
    float* __restrict__ out)
{
    extern __shared__ char smem[];
    __half* sH    = (__half*)(smem + SM_H);
    float* sBias1 = (float*)(smem + SM_BIAS);
    float* sBias2 = sBias1 + HDIM;

    const int tid  = threadIdx.x;
    const int wid  = tid >> 5;
    const int lane = tid & 31;
    const int g    = lane >> 2;
    const int tig  = lane & 3;
    const int e    = blockIdx.y;
    const int m0   = blockIdx.x * 128;

    const uint32_t smem_b = smem_u32_of(smem);

    const __half* xg  = g_Xh  + (size_t)m0 * DDIM;
    const __half* w1e = g_W1T + (size_t)e * HDIM * DDIM;
    const __half* w2e = g_W2T + (size_t)e * LOUT * HDIM;

    if (tid < HDIM) sBias1[tid] = b1[(size_t)e * HDIM + tid];
    if (tid < LOUT) sBias2[tid] = b2[(size_t)e * LOUT + tid];

    // ldmatrix lane byte offsets
    const uint32_t offA  = (uint32_t)((lane & 15) * (LDK1 * 2) + (lane >> 4) * 16);
    const uint32_t offB  = (uint32_t)(((lane & 7) + ((lane >> 4) & 1) * 8) * (LDK1 * 2) + ((lane >> 3) & 1) * 16);
    const uint32_t offA2 = (uint32_t)((lane & 15) * (LDH * 2) + (lane >> 4) * 16);
    const uint32_t offB2 = (uint32_t)(((lane & 7) + ((lane >> 4) & 1) * 8) * (LDW2 * 2) + ((lane >> 3) & 1) * 16);

    // ---------------- phase 1: 4x4 warp grid, 32x64 warp tiles ----------------
    const int wm = wid >> 2;
    const int wn = wid & 3;

    float acc[2][8][4];
    #pragma unroll
    for (int i = 0; i < 2; i++)
        #pragma unroll
        for (int j = 0; j < 8; j++)
            #pragma unroll
            for (int q = 0; q < 4; q++) acc[i][j][q] = 0.f;

    auto load_chunk1 = [&](int c, int buf) {
        uint32_t aBase = smem_b + SM_A0 + buf * 10240;
        uint32_t bBase = smem_b + SM_B0 + buf * 20480;
        {   // A: 128 rows x 32 halves
            int r = tid >> 2, q = tid & 3;
            cp16(aBase + (uint32_t)(r * (LDK1 * 2) + q * 16),
                 xg + (size_t)r * DDIM + c * 32 + q * 8);
        }
        #pragma unroll
        for (int t = 0; t < 2; t++) {   // B: 256 rows x 32 halves
            int id = tid + t * 512;
            int r = id >> 2, q = id & 3;
            cp16(bBase + (uint32_t)(r * (LDK1 * 2) + q * 16),
                 w1e + (size_t)r * DDIM + c * 32 + q * 8);
        }
        CP_COMMIT();
    };

    load_chunk1(0, 0);
    load_chunk1(1, 1);

    for (int c = 0; c < 16; c++) {
        int buf = c % 3;
        CP_WAIT(1);            // chunk c landed (at most one later group pending)
        __syncthreads();       // readers of the buffer being overwritten are done
        if (c + 2 < 16) {
            load_chunk1(c + 2, (c + 2) % 3);
        } else if (c + 2 == 16) {
            // stage W2 [64][256] single-shot into resident region
            uint32_t wBase = smem_b + SM_W2;
            #pragma unroll
            for (int t = 0; t < 4; t++) {
                int id = tid + t * 512;
                int r = id >> 5, q = id & 31;
                cp16(wBase + (uint32_t)(r * (LDW2 * 2) + q * 16),
                     w2e + (size_t)r * HDIM + q * 8);
            }
            CP_COMMIT();
        }

        const uint32_t aB = smem_b + SM_A0 + buf * 10240;
        const uint32_t bB = smem_b + SM_B0 + buf * 20480;

        #pragma unroll
        for (int ks = 0; ks < 32; ks += 16) {
            uint32_t af[2][4];
            #pragma unroll
            for (int i = 0; i < 2; i++) {
                uint32_t ad = aB + (uint32_t)(((wm * 32 + i * 16) * LDK1 + ks) * 2) + offA;
                LDMX4(af[i][0], af[i][1], af[i][2], af[i][3], ad);
            }
            uint32_t bf[8][2];
            #pragma unroll
            for (int j2 = 0; j2 < 4; j2++) {
                uint32_t bd = bB + (uint32_t)(((wn * 64 + j2 * 16) * LDK1 + ks) * 2) + offB;
                LDMX4(bf[2 * j2][0], bf[2 * j2][1], bf[2 * j2 + 1][0], bf[2 * j2 + 1][1], bd);
            }
            #pragma unroll
            for (int i = 0; i < 2; i++)
                #pragma unroll
                for (int j = 0; j < 8; j++)
                    mma_f16(acc[i][j], af[i], bf[j]);
        }
    }

    // ---- tanh(C1 + b1) -> sH (fp16), half2 stores ----
    #pragma unroll
    for (int i = 0; i < 2; i++) {
        int r0 = wm * 32 + i * 16 + g;
        #pragma unroll
        for (int j = 0; j < 8; j++) {
            int cc = wn * 64 + j * 8 + 2 * tig;
            float bb0 = sBias1[cc], bb1 = sBias1[cc + 1];
            *(__half2*)&sH[r0 * LDH + cc] =
                __floats2half2_rn(tanh_fast(acc[i][j][0] + bb0), tanh_fast(acc[i][j][1] + bb1));
            *(__half2*)&sH[(r0 + 8) * LDH + cc] =
                __floats2half2_rn(tanh_fast(acc[i][j][2] + bb0), tanh_fast(acc[i][j][3] + bb1));
        }
    }
    CP_WAIT(0);          // W2 resident
    __syncthreads();     // sH visible; phase 2 is barrier-free from here

    // ---------------- phase 2: 4x4 warp grid, 32x16 warp tiles, K=256 -------
    const int wm2 = wid >> 2;
    const int wn2 = wid & 3;

    float acc2[2][2][4];
    #pragma unroll
    for (int i = 0; i < 2; i++)
        #pragma unroll
        for (int j = 0; j < 2; j++)
            #pragma unroll
            for (int q = 0; q < 4; q++) acc2[i][j][q] = 0.f;

    const uint32_t hB = smem_b + SM_H;
    const uint32_t wB = smem_b + SM_W2;

    #pragma unroll
    for (int ks = 0; ks < 256; ks += 16) {
        uint32_t af[2][4];
        #pragma unroll
        for (int i = 0; i < 2; i++) {
            uint32_t ad = hB + (uint32_t)(((wm2 * 32 + i * 16) * LDH + ks) * 2) + offA2;
            LDMX4(af[i][0], af[i][1], af[i][2], af[i][3], ad);
        }
        uint32_t bf[4];
        uint32_t bd = wB + (uint32_t)(((wn2 * 16) * LDW2 + ks) * 2) + offB2;
        LDMX4(bf[0], bf[1], bf[2], bf[3], bd);
        #pragma unroll
        for (int i = 0; i < 2; i++) {
            mma_f16(acc2[i][0], af[i], bf);
            mma_f16(acc2[i][1], af[i], bf + 2);
        }
    }

    // ---- epilogue: out = gate * (C2 + b2) ----
    #pragma unroll
    for (int i = 0; i < 2; i++) {
        int r0 = wm2 * 32 + i * 16 + g;
        int mA = m0 + r0, mB = mA + 8;
        float gateA = g_gates[(size_t)mA * EEXP + e];
        float gateB = g_gates[(size_t)mB * EEXP + e];
        float* opA = out + ((size_t)mA * EEXP + e) * LOUT;
        float* opB = out + ((size_t)mB * EEXP + e) * LOUT;
        #pragma unroll
        for (int j = 0; j < 2; j++) {
            int cc = wn2 * 16 + j * 8 + 2 * tig;
            float bb0 = sBias2[cc], bb1 = sBias2[cc + 1];
            float2 oA, oB;
            oA.x = (acc2[i][j][0] + bb0) * gateA;
            oA.y = (acc2[i][j][1] + bb1) * gateA;
            oB.x = (acc2[i][j][2] + bb0) * gateB;
            oB.y = (acc2[i][j][3] + bb1) * gateB;
            *(float2*)(opA + cc) = oA;
            *(float2*)(opB + cc) = oB;
        }
    }
}

// ---------------------------------------------------------------------------
extern "C" void kernel_launch(void* const* d_in, const int* in_sizes, int n_in,
                              void* d_out, int out_size)
{
    const float* x       = (const float*)d_in[0];
    const float* noise   = (const float*)d_in[1];
    const float* w_gate  = (const float*)d_in[2];
    const float* w_noise = (const float*)d_in[3];
    const float* W1      = (const float*)d_in[4];
    const float* b1      = (const float*)d_in[5];
    const float* W2      = (const float*)d_in[6];
    const float* b2      = (const float*)d_in[7];
    float* out = (float*)d_out;

    __half* xh;  cudaGetSymbolAddress((void**)&xh,  g_Xh);
    __half* w1t; cudaGetSymbolAddress((void**)&w1t, g_W1T);
    __half* w2t; cudaGetSymbolAddress((void**)&w2t, g_W2T);

    cudaFuncSetAttribute(gating_kernel, cudaFuncAttributeMaxDynamicSharedMemorySize, G_SMEM);
    cudaFuncSetAttribute(moe_kernel,    cudaFuncAttributeMaxDynamicSharedMemorySize, SMEM_MOE);

    convx_kernel<<<B_ROWS * DDIM / 4 / 256, 256>>>((const float4*)x, (__half2*)xh);
    transposeh_kernel<<<dim3(HDIM / 32, DDIM / 32, EEXP), dim3(32, 8)>>>(W1, w1t, DDIM, HDIM);
    transposeh_kernel<<<dim3(LOUT / 32, HDIM / 32, EEXP), dim3(32, 8)>>>(W2, w2t, HDIM, LOUT);
    gating_kernel<<<B_ROWS / 16, 512, G_SMEM>>>(x, noise, w_gate, w_noise);
    moe_kernel<<<dim3(B_ROWS / 128, EEXP), 512, SMEM_MOE>>>(b1, b2, out);
}

// round 10
// speedup vs baseline: 1.1726x; 1.0622x over previous
#include <cuda_runtime.h>
#include <cuda_fp16.h>
#include <cstdint>
#include <math.h>

#define B_ROWS 16384
#define DDIM   512
#define EEXP   16
#define HDIM   256
#define LOUT   64

// ---------------- device scratch (allocation-free rule) ----------------
__device__ float  g_gates[B_ROWS * EEXP];
__device__ __half g_Xh [B_ROWS * DDIM];        // x, fp16
__device__ __half g_W1T[EEXP * HDIM * DDIM];   // [E][H][D], fp16
__device__ __half g_W2T[EEXP * LOUT * HDIM];   // [E][L][H], fp16

// ---------------- helpers ----------------
__device__ __forceinline__ uint32_t smem_u32_of(const void* p) {
    uint32_t a;
    asm("{ .reg .u64 t; cvta.to.shared.u64 t, %1; cvt.u32.u64 %0, t; }" : "=r"(a) : "l"(p));
    return a;
}
__device__ __forceinline__ float tanh_fast(float x) {
    float e = __expf(2.f * x);
    return 1.f - __fdividef(2.f, e + 1.f);
}
__device__ __forceinline__ float softplusf(float z) {
    return (z > 0.f) ? (z + log1pf(expf(-z))) : log1pf(expf(z));
}
__device__ __forceinline__ void cp16(uint32_t dst, const void* src) {
    asm volatile("cp.async.ca.shared.global [%0], [%1], 16;" :: "r"(dst), "l"(src));
}
#define CP_COMMIT() asm volatile("cp.async.commit_group;" ::: "memory")
#define CP_WAIT(n)  asm volatile("cp.async.wait_group %0;" :: "n"(n) : "memory")

#define LDMX4(r0, r1, r2, r3, addr) \
    asm volatile("ldmatrix.sync.aligned.m8n8.x4.shared.b16 {%0,%1,%2,%3}, [%4];" \
                 : "=r"(r0), "=r"(r1), "=r"(r2), "=r"(r3) : "r"(addr))

__device__ __forceinline__ void mma_f16(float* c, const uint32_t* a, const uint32_t* b) {
    asm volatile(
        "mma.sync.aligned.m16n8k16.row.col.f32.f16.f16.f32 "
        "{%0,%1,%2,%3}, {%4,%5,%6,%7}, {%8,%9}, {%0,%1,%2,%3};"
        : "+f"(c[0]), "+f"(c[1]), "+f"(c[2]), "+f"(c[3])
        : "r"(a[0]), "r"(a[1]), "r"(a[2]), "r"(a[3]), "r"(b[0]), "r"(b[1]));
}

// ---------------------------------------------------------------------------
// x -> fp16
// ---------------------------------------------------------------------------
__global__ __launch_bounds__(256) void convx_kernel(const float4* __restrict__ in,
                                                    __half2* __restrict__ outv)
{
    int i = blockIdx.x * 256 + threadIdx.x;
    float4 v = in[i];
    outv[2 * i]     = __floats2half2_rn(v.x, v.y);
    outv[2 * i + 1] = __floats2half2_rn(v.z, v.w);
}

// ---------------------------------------------------------------------------
// Transpose + fp16: dst[e][c][r] = half(src[e][r][c])
// ---------------------------------------------------------------------------
__global__ void transposeh_kernel(const float* __restrict__ src, __half* __restrict__ dst,
                                  int R, int C)
{
    __shared__ float t[32][33];
    int e = blockIdx.z;
    const float* s = src + (size_t)e * R * C;
    __half* d = dst + (size_t)e * R * C;
    int c0 = blockIdx.x * 32, r0 = blockIdx.y * 32;
    int tx = threadIdx.x, ty = threadIdx.y;
    #pragma unroll
    for (int i = 0; i < 32; i += 8)
        t[ty + i][tx] = s[(size_t)(r0 + ty + i) * C + c0 + tx];
    __syncthreads();
    #pragma unroll
    for (int i = 0; i < 32; i += 8)
        d[(size_t)(c0 + ty + i) * R + r0 + tx] = __float2half_rn(t[tx][ty + i]);
}

// ---------------------------------------------------------------------------
// Gating v6: 4 rows per warp (16 LDG.128 chains in flight), 256 thr / 8 warps,
// 32 rows per CTA, 512 CTAs, 2 CTAs/SM. Weights transposed in SMEM [32][516];
// w-quad LDS reused across the 4 rows. fp32-exact math (threshold safety).
// ---------------------------------------------------------------------------
#define GW_STRIDE 516
#define G_SMEM (32 * GW_STRIDE * 4)   // 66048

__global__ __launch_bounds__(256, 2) void gating_kernel(
    const float* __restrict__ x, const float* __restrict__ noise,
    const float* __restrict__ wg, const float* __restrict__ wn)
{
    extern __shared__ float sWT[];

    const int tid  = threadIdx.x;
    const int wid  = tid >> 5;
    const int lane = tid & 31;

    // transposed weights: sWT[j][d] = wg[d*16+j], sWT[16+j][d] = wn[d*16+j]
    for (int idx = tid; idx < 8192; idx += 256) {
        int d = idx >> 4, j = idx & 15;
        sWT[j * GW_STRIDE + d]        = wg[idx];
        sWT[(16 + j) * GW_STRIDE + d] = wn[idx];
    }
    __syncthreads();

    const float* wrow = sWT + lane * GW_STRIDE;
    const int r0 = blockIdx.x * 32 + wid * 4;

    const float4* xr0 = (const float4*)(x + (size_t)(r0 + 0) * DDIM);
    const float4* xr1 = (const float4*)(x + (size_t)(r0 + 1) * DDIM);
    const float4* xr2 = (const float4*)(x + (size_t)(r0 + 2) * DDIM);
    const float4* xr3 = (const float4*)(x + (size_t)(r0 + 3) * DDIM);

    float acc0 = 0.f, acc1 = 0.f, acc2 = 0.f, acc3 = 0.f;
    #pragma unroll 4
    for (int q = 0; q < 128; q++) {
        float4 w  = *(const float4*)(wrow + q * 4);   // reused by 4 rows
        float4 v0 = __ldg(xr0 + q);
        float4 v1 = __ldg(xr1 + q);
        float4 v2 = __ldg(xr2 + q);
        float4 v3 = __ldg(xr3 + q);
        acc0 = fmaf(v0.x, w.x, acc0); acc0 = fmaf(v0.y, w.y, acc0);
        acc0 = fmaf(v0.z, w.z, acc0); acc0 = fmaf(v0.w, w.w, acc0);
        acc1 = fmaf(v1.x, w.x, acc1); acc1 = fmaf(v1.y, w.y, acc1);
        acc1 = fmaf(v1.z, w.z, acc1); acc1 = fmaf(v1.w, w.w, acc1);
        acc2 = fmaf(v2.x, w.x, acc2); acc2 = fmaf(v2.y, w.y, acc2);
        acc2 = fmaf(v2.z, w.z, acc2); acc2 = fmaf(v2.w, w.w, acc2);
        acc3 = fmaf(v3.x, w.x, acc3); acc3 = fmaf(v3.y, w.y, acc3);
        acc3 = fmaf(v3.z, w.z, acc3); acc3 = fmaf(v3.w, w.w, acc3);
    }

    float accs[4] = { acc0, acc1, acc2, acc3 };
    #pragma unroll
    for (int rr = 0; rr < 4; rr++) {
        int r = r0 + rr;
        float acc = accs[rr];

        // lanes 0..15: clean logits; lanes 16..31: noise pre-activation
        float accN = __shfl_down_sync(0xffffffffu, acc, 16);
        float logit = 0.f;
        if (lane < 16) {
            float stddev = softplusf(accN) + 0.01f;
            logit = fmaf(noise[(size_t)r * EEXP + lane], stddev, acc);
        }
        float m = logit;
        #pragma unroll
        for (int o = 8; o; o >>= 1) m = fmaxf(m, __shfl_xor_sync(0xffffffffu, m, o, 16));
        float pr = expf(logit - m);
        float s = pr;
        #pragma unroll
        for (int o = 8; o; o >>= 1) s += __shfl_xor_sync(0xffffffffu, s, o, 16);
        float prob = pr / s;
        float s2 = prob;
        #pragma unroll
        for (int o = 8; o; o >>= 1) s2 += __shfl_xor_sync(0xffffffffu, s2, o, 16);
        float meanw = s2 * (1.f / 16.f) - 1e-8f;
        float gv = (prob >= meanw) ? prob : 0.f;
        float gs = gv;
        #pragma unroll
        for (int o = 8; o; o >>= 1) gs += __shfl_xor_sync(0xffffffffu, gs, o, 16);

        if (lane < 16)
            g_gates[(size_t)r * EEXP + lane] = gv / gs;
    }
}

// ---------------------------------------------------------------------------
// Fused expert MLP v6 (unchanged from R9): fp16 mma + 3-stage cp.async
// pipeline, resident W2, barrier-free phase 2.
// ---------------------------------------------------------------------------
#define SM_H     0              // 128*264*2 = 67584
#define SM_A0    67584          // 128*40*2  = 10240 (x3)
#define SM_B0    98304          // 256*40*2  = 20480 (x3)
#define SM_W2    159744         // 64*264*2  = 33792
#define SM_BIAS  193536         // 256f + 64f = 1280
#define SMEM_MOE 194816

#define LDK1 40   // phase-1 tile stride (halves)
#define LDH  264  // h tile stride (halves)
#define LDW2 264  // W2 tile stride (halves)

__global__ __launch_bounds__(512, 1) void moe_kernel(
    const float* __restrict__ b1, const float* __restrict__ b2,
    float* __restrict__ out)
{
    extern __shared__ char smem[];
    __half* sH    = (__half*)(smem + SM_H);
    float* sBias1 = (float*)(smem + SM_BIAS);
    float* sBias2 = sBias1 + HDIM;

    const int tid  = threadIdx.x;
    const int wid  = tid >> 5;
    const int lane = tid & 31;
    const int g    = lane >> 2;
    const int tig  = lane & 3;
    const int e    = blockIdx.y;
    const int m0   = blockIdx.x * 128;

    const uint32_t smem_b = smem_u32_of(smem);

    const __half* xg  = g_Xh  + (size_t)m0 * DDIM;
    const __half* w1e = g_W1T + (size_t)e * HDIM * DDIM;
    const __half* w2e = g_W2T + (size_t)e * LOUT * HDIM;

    if (tid < HDIM) sBias1[tid] = b1[(size_t)e * HDIM + tid];
    if (tid < LOUT) sBias2[tid] = b2[(size_t)e * LOUT + tid];

    // ldmatrix lane byte offsets
    const uint32_t offA  = (uint32_t)((lane & 15) * (LDK1 * 2) + (lane >> 4) * 16);
    const uint32_t offB  = (uint32_t)(((lane & 7) + ((lane >> 4) & 1) * 8) * (LDK1 * 2) + ((lane >> 3) & 1) * 16);
    const uint32_t offA2 = (uint32_t)((lane & 15) * (LDH * 2) + (lane >> 4) * 16);
    const uint32_t offB2 = (uint32_t)(((lane & 7) + ((lane >> 4) & 1) * 8) * (LDW2 * 2) + ((lane >> 3) & 1) * 16);

    // ---------------- phase 1: 4x4 warp grid, 32x64 warp tiles ----------------
    const int wm = wid >> 2;
    const int wn = wid & 3;

    float acc[2][8][4];
    #pragma unroll
    for (int i = 0; i < 2; i++)
        #pragma unroll
        for (int j = 0; j < 8; j++)
            #pragma unroll
            for (int q = 0; q < 4; q++) acc[i][j][q] = 0.f;

    auto load_chunk1 = [&](int c, int buf) {
        uint32_t aBase = smem_b + SM_A0 + buf * 10240;
        uint32_t bBase = smem_b + SM_B0 + buf * 20480;
        {   // A: 128 rows x 32 halves
            int r = tid >> 2, q = tid & 3;
            cp16(aBase + (uint32_t)(r * (LDK1 * 2) + q * 16),
                 xg + (size_t)r * DDIM + c * 32 + q * 8);
        }
        #pragma unroll
        for (int t = 0; t < 2; t++) {   // B: 256 rows x 32 halves
            int id = tid + t * 512;
            int r = id >> 2, q = id & 3;
            cp16(bBase + (uint32_t)(r * (LDK1 * 2) + q * 16),
                 w1e + (size_t)r * DDIM + c * 32 + q * 8);
        }
        CP_COMMIT();
    };

    load_chunk1(0, 0);
    load_chunk1(1, 1);

    for (int c = 0; c < 16; c++) {
        int buf = c % 3;
        CP_WAIT(1);            // chunk c landed (at most one later group pending)
        __syncthreads();       // readers of the buffer being overwritten are done
        if (c + 2 < 16) {
            load_chunk1(c + 2, (c + 2) % 3);
        } else if (c + 2 == 16) {
            // stage W2 [64][256] single-shot into resident region
            uint32_t wBase = smem_b + SM_W2;
            #pragma unroll
            for (int t = 0; t < 4; t++) {
                int id = tid + t * 512;
                int r = id >> 5, q = id & 31;
                cp16(wBase + (uint32_t)(r * (LDW2 * 2) + q * 16),
                     w2e + (size_t)r * HDIM + q * 8);
            }
            CP_COMMIT();
        }

        const uint32_t aB = smem_b + SM_A0 + buf * 10240;
        const uint32_t bB = smem_b + SM_B0 + buf * 20480;

        #pragma unroll
        for (int ks = 0; ks < 32; ks += 16) {
            uint32_t af[2][4];
            #pragma unroll
            for (int i = 0; i < 2; i++) {
                uint32_t ad = aB + (uint32_t)(((wm * 32 + i * 16) * LDK1 + ks) * 2) + offA;
                LDMX4(af[i][0], af[i][1], af[i][2], af[i][3], ad);
            }
            uint32_t bf[8][2];
            #pragma unroll
            for (int j2 = 0; j2 < 4; j2++) {
                uint32_t bd = bB + (uint32_t)(((wn * 64 + j2 * 16) * LDK1 + ks) * 2) + offB;
                LDMX4(bf[2 * j2][0], bf[2 * j2][1], bf[2 * j2 + 1][0], bf[2 * j2 + 1][1], bd);
            }
            #pragma unroll
            for (int i = 0; i < 2; i++)
                #pragma unroll
                for (int j = 0; j < 8; j++)
                    mma_f16(acc[i][j], af[i], bf[j]);
        }
    }

    // ---- tanh(C1 + b1) -> sH (fp16), half2 stores ----
    #pragma unroll
    for (int i = 0; i < 2; i++) {
        int r0 = wm * 32 + i * 16 + g;
        #pragma unroll
        for (int j = 0; j < 8; j++) {
            int cc = wn * 64 + j * 8 + 2 * tig;
            float bb0 = sBias1[cc], bb1 = sBias1[cc + 1];
            *(__half2*)&sH[r0 * LDH + cc] =
                __floats2half2_rn(tanh_fast(acc[i][j][0] + bb0), tanh_fast(acc[i][j][1] + bb1));
            *(__half2*)&sH[(r0 + 8) * LDH + cc] =
                __floats2half2_rn(tanh_fast(acc[i][j][2] + bb0), tanh_fast(acc[i][j][3] + bb1));
        }
    }
    CP_WAIT(0);          // W2 resident
    __syncthreads();     // sH visible; phase 2 is barrier-free from here

    // ---------------- phase 2: 4x4 warp grid, 32x16 warp tiles, K=256 -------
    const int wm2 = wid >> 2;
    const int wn2 = wid & 3;

    float acc2[2][2][4];
    #pragma unroll
    for (int i = 0; i < 2; i++)
        #pragma unroll
        for (int j = 0; j < 2; j++)
            #pragma unroll
            for (int q = 0; q < 4; q++) acc2[i][j][q] = 0.f;

    const uint32_t hB = smem_b + SM_H;
    const uint32_t wB = smem_b + SM_W2;

    #pragma unroll
    for (int ks = 0; ks < 256; ks += 16) {
        uint32_t af[2][4];
        #pragma unroll
        for (int i = 0; i < 2; i++) {
            uint32_t ad = hB + (uint32_t)(((wm2 * 32 + i * 16) * LDH + ks) * 2) + offA2;
            LDMX4(af[i][0], af[i][1], af[i][2], af[i][3], ad);
        }
        uint32_t bf[4];
        uint32_t bd = wB + (uint32_t)(((wn2 * 16) * LDW2 + ks) * 2) + offB2;
        LDMX4(bf[0], bf[1], bf[2], bf[3], bd);
        #pragma unroll
        for (int i = 0; i < 2; i++) {
            mma_f16(acc2[i][0], af[i], bf);
            mma_f16(acc2[i][1], af[i], bf + 2);
        }
    }

    // ---- epilogue: out = gate * (C2 + b2) ----
    #pragma unroll
    for (int i = 0; i < 2; i++) {
        int r0 = wm2 * 32 + i * 16 + g;
        int mA = m0 + r0, mB = mA + 8;
        float gateA = g_gates[(size_t)mA * EEXP + e];
        float gateB = g_gates[(size_t)mB * EEXP + e];
        float* opA = out + ((size_t)mA * EEXP + e) * LOUT;
        float* opB = out + ((size_t)mB * EEXP + e) * LOUT;
        #pragma unroll
        for (int j = 0; j < 2; j++) {
            int cc = wn2 * 16 + j * 8 + 2 * tig;
            float bb0 = sBias2[cc], bb1 = sBias2[cc + 1];
            float2 oA, oB;
            oA.x = (acc2[i][j][0] + bb0) * gateA;
            oA.y = (acc2[i][j][1] + bb1) * gateA;
            oB.x = (acc2[i][j][2] + bb0) * gateB;
            oB.y = (acc2[i][j][3] + bb1) * gateB;
            *(float2*)(opA + cc) = oA;
            *(float2*)(opB + cc) = oB;
        }
    }
}

// ---------------------------------------------------------------------------
extern "C" void kernel_launch(void* const* d_in, const int* in_sizes, int n_in,
                              void* d_out, int out_size)
{
    const float* x       = (const float*)d_in[0];
    const float* noise   = (const float*)d_in[1];
    const float* w_gate  = (const float*)d_in[2];
    const float* w_noise = (const float*)d_in[3];
    const float* W1      = (const float*)d_in[4];
    const float* b1      = (const float*)d_in[5];
    const float* W2      = (const float*)d_in[6];
    const float* b2      = (const float*)d_in[7];
    float* out = (float*)d_out;

    __half* xh;  cudaGetSymbolAddress((void**)&xh,  g_Xh);
    __half* w1t; cudaGetSymbolAddress((void**)&w1t, g_W1T);
    __half* w2t; cudaGetSymbolAddress((void**)&w2t, g_W2T);

    cudaFuncSetAttribute(gating_kernel, cudaFuncAttributeMaxDynamicSharedMemorySize, G_SMEM);
    cudaFuncSetAttribute(moe_kernel,    cudaFuncAttributeMaxDynamicSharedMemorySize, SMEM_MOE);

    convx_kernel<<<B_ROWS * DDIM / 4 / 256, 256>>>((const float4*)x, (__half2*)xh);
    transposeh_kernel<<<dim3(HDIM / 32, DDIM / 32, EEXP), dim3(32, 8)>>>(W1, w1t, DDIM, HDIM);
    transposeh_kernel<<<dim3(LOUT / 32, HDIM / 32, EEXP), dim3(32, 8)>>>(W2, w2t, HDIM, LOUT);
    gating_kernel<<<B_ROWS / 32, 256, G_SMEM>>>(x, noise, w_gate, w_noise);
    moe_kernel<<<dim3(B_ROWS / 128, EEXP), 512, SMEM_MOE>>>(b1, b2, out);
}

// round 11
// speedup vs baseline: 2.1134x; 1.8022x over previous
#include <cuda_runtime.h>
#include <cuda_fp16.h>
#include <cstdint>
#include <math.h>

#define B_ROWS 16384
#define DDIM   512
#define EEXP   16
#define HDIM   256
#define LOUT   64

// ---------------- device scratch (allocation-free rule) ----------------
__device__ float  g_gates[B_ROWS * EEXP];
__device__ int    g_counts[EEXP];
__device__ int    g_rows[EEXP * B_ROWS];
__device__ __half g_Xh [B_ROWS * DDIM];        // x, fp16
__device__ __half g_W1T[EEXP * HDIM * DDIM];   // [E][H][D], fp16
__device__ __half g_W2T[EEXP * LOUT * HDIM];   // [E][L][H], fp16

// ---------------- helpers ----------------
__device__ __forceinline__ uint32_t smem_u32_of(const void* p) {
    uint32_t a;
    asm("{ .reg .u64 t; cvta.to.shared.u64 t, %1; cvt.u32.u64 %0, t; }" : "=r"(a) : "l"(p));
    return a;
}
__device__ __forceinline__ float tanh_fast(float x) {
    float e = __expf(2.f * x);
    return 1.f - __fdividef(2.f, e + 1.f);
}
__device__ __forceinline__ float softplusf(float z) {
    return (z > 0.f) ? (z + log1pf(expf(-z))) : log1pf(expf(z));
}
__device__ __forceinline__ void cp16(uint32_t dst, const void* src) {
    asm volatile("cp.async.ca.shared.global [%0], [%1], 16;" :: "r"(dst), "l"(src));
}
#define CP_COMMIT() asm volatile("cp.async.commit_group;" ::: "memory")
#define CP_WAIT(n)  asm volatile("cp.async.wait_group %0;" :: "n"(n) : "memory")

#define LDMX4(r0, r1, r2, r3, addr) \
    asm volatile("ldmatrix.sync.aligned.m8n8.x4.shared.b16 {%0,%1,%2,%3}, [%4];" \
                 : "=r"(r0), "=r"(r1), "=r"(r2), "=r"(r3) : "r"(addr))

__device__ __forceinline__ void mma_f16(float* c, const uint32_t* a, const uint32_t* b) {
    asm volatile(
        "mma.sync.aligned.m16n8k16.row.col.f32.f16.f16.f32 "
        "{%0,%1,%2,%3}, {%4,%5,%6,%7}, {%8,%9}, {%0,%1,%2,%3};"
        : "+f"(c[0]), "+f"(c[1]), "+f"(c[2]), "+f"(c[3])
        : "r"(a[0]), "r"(a[1]), "r"(a[2]), "r"(a[3]), "r"(b[0]), "r"(b[1]));
}

// ---------------------------------------------------------------------------
// Zero-fill d_out + reset per-expert counters (graph-replay safe).
// ---------------------------------------------------------------------------
__global__ __launch_bounds__(256) void zerofill_kernel(float4* __restrict__ out)
{
    const float4 z = make_float4(0.f, 0.f, 0.f, 0.f);
    size_t base = (size_t)blockIdx.x * 1024 + threadIdx.x;
    #pragma unroll
    for (int t = 0; t < 4; t++) out[base + t * 256] = z;
    if (blockIdx.x == 0 && threadIdx.x < EEXP) g_counts[threadIdx.x] = 0;
}

// ---------------------------------------------------------------------------
// x -> fp16
// ---------------------------------------------------------------------------
__global__ __launch_bounds__(256) void convx_kernel(const float4* __restrict__ in,
                                                    __half2* __restrict__ outv)
{
    int i = blockIdx.x * 256 + threadIdx.x;
    float4 v = in[i];
    outv[2 * i]     = __floats2half2_rn(v.x, v.y);
    outv[2 * i + 1] = __floats2half2_rn(v.z, v.w);
}

// ---------------------------------------------------------------------------
// Transpose + fp16: dst[e][c][r] = half(src[e][r][c])
// ---------------------------------------------------------------------------
__global__ void transposeh_kernel(const float* __restrict__ src, __half* __restrict__ dst,
                                  int R, int C)
{
    __shared__ float t[32][33];
    int e = blockIdx.z;
    const float* s = src + (size_t)e * R * C;
    __half* d = dst + (size_t)e * R * C;
    int c0 = blockIdx.x * 32, r0 = blockIdx.y * 32;
    int tx = threadIdx.x, ty = threadIdx.y;
    #pragma unroll
    for (int i = 0; i < 32; i += 8)
        t[ty + i][tx] = s[(size_t)(r0 + ty + i) * C + c0 + tx];
    __syncthreads();
    #pragma unroll
    for (int i = 0; i < 32; i += 8)
        d[(size_t)(c0 + ty + i) * R + r0 + tx] = __float2half_rn(t[tx][ty + i]);
}

// ---------------------------------------------------------------------------
// Gating v6 + sparse-dispatch compaction.
// 4 rows per warp, 256 thr / 8 warps, 512 CTAs. fp32-exact math.
// Rows with gate>0 appended to g_rows[e] (order-free, value-deterministic).
// ---------------------------------------------------------------------------
#define GW_STRIDE 516
#define G_SMEM (32 * GW_STRIDE * 4)   // 66048

__global__ __launch_bounds__(256, 2) void gating_kernel(
    const float* __restrict__ x, const float* __restrict__ noise,
    const float* __restrict__ wg, const float* __restrict__ wn)
{
    extern __shared__ float sWT[];

    const int tid  = threadIdx.x;
    const int wid  = tid >> 5;
    const int lane = tid & 31;

    for (int idx = tid; idx < 8192; idx += 256) {
        int d = idx >> 4, j = idx & 15;
        sWT[j * GW_STRIDE + d]        = wg[idx];
        sWT[(16 + j) * GW_STRIDE + d] = wn[idx];
    }
    __syncthreads();

    const float* wrow = sWT + lane * GW_STRIDE;
    const int r0 = blockIdx.x * 32 + wid * 4;

    const float4* xr0 = (const float4*)(x + (size_t)(r0 + 0) * DDIM);
    const float4* xr1 = (const float4*)(x + (size_t)(r0 + 1) * DDIM);
    const float4* xr2 = (const float4*)(x + (size_t)(r0 + 2) * DDIM);
    const float4* xr3 = (const float4*)(x + (size_t)(r0 + 3) * DDIM);

    float acc0 = 0.f, acc1 = 0.f, acc2 = 0.f, acc3 = 0.f;
    #pragma unroll 4
    for (int q = 0; q < 128; q++) {
        float4 w  = *(const float4*)(wrow + q * 4);
        float4 v0 = __ldg(xr0 + q);
        float4 v1 = __ldg(xr1 + q);
        float4 v2 = __ldg(xr2 + q);
        float4 v3 = __ldg(xr3 + q);
        acc0 = fmaf(v0.x, w.x, acc0); acc0 = fmaf(v0.y, w.y, acc0);
        acc0 = fmaf(v0.z, w.z, acc0); acc0 = fmaf(v0.w, w.w, acc0);
        acc1 = fmaf(v1.x, w.x, acc1); acc1 = fmaf(v1.y, w.y, acc1);
        acc1 = fmaf(v1.z, w.z, acc1); acc1 = fmaf(v1.w, w.w, acc1);
        acc2 = fmaf(v2.x, w.x, acc2); acc2 = fmaf(v2.y, w.y, acc2);
        acc2 = fmaf(v2.z, w.z, acc2); acc2 = fmaf(v2.w, w.w, acc2);
        acc3 = fmaf(v3.x, w.x, acc3); acc3 = fmaf(v3.y, w.y, acc3);
        acc3 = fmaf(v3.z, w.z, acc3); acc3 = fmaf(v3.w, w.w, acc3);
    }

    float accs[4] = { acc0, acc1, acc2, acc3 };
    #pragma unroll
    for (int rr = 0; rr < 4; rr++) {
        int r = r0 + rr;
        float acc = accs[rr];

        float accN = __shfl_down_sync(0xffffffffu, acc, 16);
        float logit = 0.f;
        if (lane < 16) {
            float stddev = softplusf(accN) + 0.01f;
            logit = fmaf(noise[(size_t)r * EEXP + lane], stddev, acc);
        }
        float m = logit;
        #pragma unroll
        for (int o = 8; o; o >>= 1) m = fmaxf(m, __shfl_xor_sync(0xffffffffu, m, o, 16));
        float pr = expf(logit - m);
        float s = pr;
        #pragma unroll
        for (int o = 8; o; o >>= 1) s += __shfl_xor_sync(0xffffffffu, s, o, 16);
        float prob = pr / s;
        float s2 = prob;
        #pragma unroll
        for (int o = 8; o; o >>= 1) s2 += __shfl_xor_sync(0xffffffffu, s2, o, 16);
        float meanw = s2 * (1.f / 16.f) - 1e-8f;
        float gv = (prob >= meanw) ? prob : 0.f;
        float gs = gv;
        #pragma unroll
        for (int o = 8; o; o >>= 1) gs += __shfl_xor_sync(0xffffffffu, gs, o, 16);

        if (lane < 16) {
            g_gates[(size_t)r * EEXP + lane] = gv / gs;
            if (gv > 0.f) {
                int pos = atomicAdd(&g_counts[lane], 1);
                g_rows[lane * B_ROWS + pos] = r;
            }
        }
    }
}

// ---------------------------------------------------------------------------
// Fused expert MLP v7: v6 + sparse row dispatch.
// CTA = (tile t of expert e's compacted rows). Early-exit when t*128 >= count.
// A tiles gathered via SMEM row list; epilogue scatters only valid rows.
// ---------------------------------------------------------------------------
#define SM_H     0              // 128*264*2 = 67584
#define SM_A0    67584          // 128*40*2  = 10240 (x3)
#define SM_B0    98304          // 256*40*2  = 20480 (x3)
#define SM_W2    159744         // 64*264*2  = 33792
#define SM_BIAS  193536         // 256f + 64f = 1280
#define SM_ROWS  194816         // 128 ints = 512
#define SMEM_MOE 195328

#define LDK1 40   // phase-1 tile stride (halves)
#define LDH  264  // h tile stride (halves)
#define LDW2 264  // W2 tile stride (halves)

__global__ __launch_bounds__(512, 1) void moe_kernel(
    const float* __restrict__ b1, const float* __restrict__ b2,
    float* __restrict__ out)
{
    extern __shared__ char smem[];
    __half* sH    = (__half*)(smem + SM_H);
    float* sBias1 = (float*)(smem + SM_BIAS);
    float* sBias2 = sBias1 + HDIM;
    int*   sRows  = (int*)(smem + SM_ROWS);

    const int e   = blockIdx.y;
    const int m0  = blockIdx.x * 128;
    const int cnt = g_counts[e];
    if (m0 >= cnt) return;

    const int tid  = threadIdx.x;
    const int wid  = tid >> 5;
    const int lane = tid & 31;
    const int g    = lane >> 2;
    const int tig  = lane & 3;

    const uint32_t smem_b = smem_u32_of(smem);

    const __half* w1e = g_W1T + (size_t)e * HDIM * DDIM;
    const __half* w2e = g_W2T + (size_t)e * LOUT * HDIM;

    if (tid < 128) {
        int p = m0 + tid;
        sRows[tid] = g_rows[e * B_ROWS + (p < cnt ? p : cnt - 1)];
    }
    if (tid < HDIM) sBias1[tid] = b1[(size_t)e * HDIM + tid];
    if (tid < LOUT) sBias2[tid] = b2[(size_t)e * LOUT + tid];
    __syncthreads();   // sRows visible before gathered cp.async

    // ldmatrix lane byte offsets
    const uint32_t offA  = (uint32_t)((lane & 15) * (LDK1 * 2) + (lane >> 4) * 16);
    const uint32_t offB  = (uint32_t)(((lane & 7) + ((lane >> 4) & 1) * 8) * (LDK1 * 2) + ((lane >> 3) & 1) * 16);
    const uint32_t offA2 = (uint32_t)((lane & 15) * (LDH * 2) + (lane >> 4) * 16);
    const uint32_t offB2 = (uint32_t)(((lane & 7) + ((lane >> 4) & 1) * 8) * (LDW2 * 2) + ((lane >> 3) & 1) * 16);

    // ---------------- phase 1: 4x4 warp grid, 32x64 warp tiles ----------------
    const int wm = wid >> 2;
    const int wn = wid & 3;

    float acc[2][8][4];
    #pragma unroll
    for (int i = 0; i < 2; i++)
        #pragma unroll
        for (int j = 0; j < 8; j++)
            #pragma unroll
            for (int q = 0; q < 4; q++) acc[i][j][q] = 0.f;

    auto load_chunk1 = [&](int c, int buf) {
        uint32_t aBase = smem_b + SM_A0 + buf * 10240;
        uint32_t bBase = smem_b + SM_B0 + buf * 20480;
        {   // A: 128 gathered rows x 32 halves
            int r = tid >> 2, q = tid & 3;
            const __half* src = g_Xh + (size_t)sRows[r] * DDIM + c * 32 + q * 8;
            cp16(aBase + (uint32_t)(r * (LDK1 * 2) + q * 16), src);
        }
        #pragma unroll
        for (int t = 0; t < 2; t++) {   // B: 256 rows x 32 halves
            int id = tid + t * 512;
            int r = id >> 2, q = id & 3;
            cp16(bBase + (uint32_t)(r * (LDK1 * 2) + q * 16),
                 w1e + (size_t)r * DDIM + c * 32 + q * 8);
        }
        CP_COMMIT();
    };

    load_chunk1(0, 0);
    load_chunk1(1, 1);

    for (int c = 0; c < 16; c++) {
        int buf = c % 3;
        CP_WAIT(1);
        __syncthreads();
        if (c + 2 < 16) {
            load_chunk1(c + 2, (c + 2) % 3);
        } else if (c + 2 == 16) {
            uint32_t wBase = smem_b + SM_W2;
            #pragma unroll
            for (int t = 0; t < 4; t++) {
                int id = tid + t * 512;
                int r = id >> 5, q = id & 31;
                cp16(wBase + (uint32_t)(r * (LDW2 * 2) + q * 16),
                     w2e + (size_t)r * HDIM + q * 8);
            }
            CP_COMMIT();
        }

        const uint32_t aB = smem_b + SM_A0 + buf * 10240;
        const uint32_t bB = smem_b + SM_B0 + buf * 20480;

        #pragma unroll
        for (int ks = 0; ks < 32; ks += 16) {
            uint32_t af[2][4];
            #pragma unroll
            for (int i = 0; i < 2; i++) {
                uint32_t ad = aB + (uint32_t)(((wm * 32 + i * 16) * LDK1 + ks) * 2) + offA;
                LDMX4(af[i][0], af[i][1], af[i][2], af[i][3], ad);
            }
            uint32_t bf[8][2];
            #pragma unroll
            for (int j2 = 0; j2 < 4; j2++) {
                uint32_t bd = bB + (uint32_t)(((wn * 64 + j2 * 16) * LDK1 + ks) * 2) + offB;
                LDMX4(bf[2 * j2][0], bf[2 * j2][1], bf[2 * j2 + 1][0], bf[2 * j2 + 1][1], bd);
            }
            #pragma unroll
            for (int i = 0; i < 2; i++)
                #pragma unroll
                for (int j = 0; j < 8; j++)
                    mma_f16(acc[i][j], af[i], bf[j]);
        }
    }

    // ---- tanh(C1 + b1) -> sH (fp16), half2 stores ----
    #pragma unroll
    for (int i = 0; i < 2; i++) {
        int r0 = wm * 32 + i * 16 + g;
        #pragma unroll
        for (int j = 0; j < 8; j++) {
            int cc = wn * 64 + j * 8 + 2 * tig;
            float bb0 = sBias1[cc], bb1 = sBias1[cc + 1];
            *(__half2*)&sH[r0 * LDH + cc] =
                __floats2half2_rn(tanh_fast(acc[i][j][0] + bb0), tanh_fast(acc[i][j][1] + bb1));
            *(__half2*)&sH[(r0 + 8) * LDH + cc] =
                __floats2half2_rn(tanh_fast(acc[i][j][2] + bb0), tanh_fast(acc[i][j][3] + bb1));
        }
    }
    CP_WAIT(0);          // W2 resident
    __syncthreads();     // sH visible; phase 2 is barrier-free from here

    // ---------------- phase 2: 4x4 warp grid, 32x16 warp tiles, K=256 -------
    const int wm2 = wid >> 2;
    const int wn2 = wid & 3;

    float acc2[2][2][4];
    #pragma unroll
    for (int i = 0; i < 2; i++)
        #pragma unroll
        for (int j = 0; j < 2; j++)
            #pragma unroll
            for (int q = 0; q < 4; q++) acc2[i][j][q] = 0.f;

    const uint32_t hB = smem_b + SM_H;
    const uint32_t wB = smem_b + SM_W2;

    #pragma unroll
    for (int ks = 0; ks < 256; ks += 16) {
        uint32_t af[2][4];
        #pragma unroll
        for (int i = 0; i < 2; i++) {
            uint32_t ad = hB + (uint32_t)(((wm2 * 32 + i * 16) * LDH + ks) * 2) + offA2;
            LDMX4(af[i][0], af[i][1], af[i][2], af[i][3], ad);
        }
        uint32_t bf[4];
        uint32_t bd = wB + (uint32_t)(((wn2 * 16) * LDW2 + ks) * 2) + offB2;
        LDMX4(bf[0], bf[1], bf[2], bf[3], bd);
        #pragma unroll
        for (int i = 0; i < 2; i++) {
            mma_f16(acc2[i][0], af[i], bf);
            mma_f16(acc2[i][1], af[i], bf + 2);
        }
    }

    // ---- epilogue: scatter out[row, e] = gate * (C2 + b2), valid rows only ----
    #pragma unroll
    for (int i = 0; i < 2; i++) {
        int p0 = wm2 * 32 + i * 16 + g;   // local positions p0, p0+8
        #pragma unroll
        for (int h = 0; h < 2; h++) {
            int p = p0 + h * 8;
            if (m0 + p < cnt) {
                int row = sRows[p];
                float gate = g_gates[(size_t)row * EEXP + e];
                float* op = out + ((size_t)row * EEXP + e) * LOUT;
                #pragma unroll
                for (int j = 0; j < 2; j++) {
                    int cc = wn2 * 16 + j * 8 + 2 * tig;
                    float2 o;
                    o.x = (acc2[i][j][2 * h + 0] + sBias2[cc])     * gate;
                    o.y = (acc2[i][j][2 * h + 1] + sBias2[cc + 1]) * gate;
                    *(float2*)(op + cc) = o;
                }
            }
        }
    }
}

// ---------------------------------------------------------------------------
extern "C" void kernel_launch(void* const* d_in, const int* in_sizes, int n_in,
                              void* d_out, int out_size)
{
    const float* x       = (const float*)d_in[0];
    const float* noise   = (const float*)d_in[1];
    const float* w_gate  = (const float*)d_in[2];
    const float* w_noise = (const float*)d_in[3];
    const float* W1      = (const float*)d_in[4];
    const float* b1      = (const float*)d_in[5];
    const float* W2      = (const float*)d_in[6];
    const float* b2      = (const float*)d_in[7];
    float* out = (float*)d_out;

    __half* xh;  cudaGetSymbolAddress((void**)&xh,  g_Xh);
    __half* w1t; cudaGetSymbolAddress((void**)&w1t, g_W1T);
    __half* w2t; cudaGetSymbolAddress((void**)&w2t, g_W2T);

    cudaFuncSetAttribute(gating_kernel, cudaFuncAttributeMaxDynamicSharedMemorySize, G_SMEM);
    cudaFuncSetAttribute(moe_kernel,    cudaFuncAttributeMaxDynamicSharedMemorySize, SMEM_MOE);

    zerofill_kernel<<<B_ROWS * EEXP * LOUT / 4 / 1024, 256>>>((float4*)out);
    convx_kernel<<<B_ROWS * DDIM / 4 / 256, 256>>>((const float4*)x, (__half2*)xh);
    transposeh_kernel<<<dim3(HDIM / 32, DDIM / 32, EEXP), dim3(32, 8)>>>(W1, w1t, DDIM, HDIM);
    transposeh_kernel<<<dim3(LOUT / 32, HDIM / 32, EEXP), dim3(32, 8)>>>(W2, w2t, HDIM, LOUT);
    gating_kernel<<<B_ROWS / 32, 256, G_SMEM>>>(x, noise, w_gate, w_noise);
    moe_kernel<<<dim3(B_ROWS / 128, EEXP), 512, SMEM_MOE>>>(b1, b2, out);
}

// round 12
// speedup vs baseline: 2.7990x; 1.3244x over previous
#include <cuda_runtime.h>
#include <cuda_fp16.h>
#include <cstdint>
#include <math.h>

#define B_ROWS 16384
#define DDIM   512
#define EEXP   16
#define HDIM   256
#define LOUT   64

// ---------------- device scratch (allocation-free rule) ----------------
__device__ float  g_gates[B_ROWS * EEXP];
__device__ int    g_counts[EEXP];
__device__ int    g_rows[EEXP * B_ROWS];
__device__ __half g_Xh [B_ROWS * DDIM];        // x hi, fp16
__device__ __half g_Xlo[B_ROWS * DDIM];        // (x - hi)*2048, fp16
__device__ __half g_W1T[EEXP * HDIM * DDIM];   // [E][H][D], fp16
__device__ __half g_W2T[EEXP * LOUT * HDIM];   // [E][L][H], fp16
__device__ __half g_WcHi[32 * DDIM];           // gating weights [32 cols][512], hi
__device__ __half g_WcLo[32 * DDIM];           // (w - hi)*2048

// ---------------- helpers ----------------
__device__ __forceinline__ uint32_t smem_u32_of(const void* p) {
    uint32_t a;
    asm("{ .reg .u64 t; cvta.to.shared.u64 t, %1; cvt.u32.u64 %0, t; }" : "=r"(a) : "l"(p));
    return a;
}
__device__ __forceinline__ float tanh_fast(float x) {
    float e = __expf(2.f * x);
    return 1.f - __fdividef(2.f, e + 1.f);
}
__device__ __forceinline__ float softplusf(float z) {
    return (z > 0.f) ? (z + log1pf(expf(-z))) : log1pf(expf(z));
}
__device__ __forceinline__ void cp16(uint32_t dst, const void* src) {
    asm volatile("cp.async.ca.shared.global [%0], [%1], 16;" :: "r"(dst), "l"(src));
}
#define CP_COMMIT() asm volatile("cp.async.commit_group;" ::: "memory")
#define CP_WAIT(n)  asm volatile("cp.async.wait_group %0;" :: "n"(n) : "memory")

#define LDMX4(r0, r1, r2, r3, addr) \
    asm volatile("ldmatrix.sync.aligned.m8n8.x4.shared.b16 {%0,%1,%2,%3}, [%4];" \
                 : "=r"(r0), "=r"(r1), "=r"(r2), "=r"(r3) : "r"(addr))

__device__ __forceinline__ void mma_f16(float* c, const uint32_t* a, const uint32_t* b) {
    asm volatile(
        "mma.sync.aligned.m16n8k16.row.col.f32.f16.f16.f32 "
        "{%0,%1,%2,%3}, {%4,%5,%6,%7}, {%8,%9}, {%0,%1,%2,%3};"
        : "+f"(c[0]), "+f"(c[1]), "+f"(c[2]), "+f"(c[3])
        : "r"(a[0]), "r"(a[1]), "r"(a[2]), "r"(a[3]), "r"(b[0]), "r"(b[1]));
}

// ---------------------------------------------------------------------------
// Zero-fill d_out + reset per-expert counters (graph-replay safe).
// ---------------------------------------------------------------------------
__global__ __launch_bounds__(256) void zerofill_kernel(float4* __restrict__ out)
{
    const float4 z = make_float4(0.f, 0.f, 0.f, 0.f);
    size_t base = (size_t)blockIdx.x * 1024 + threadIdx.x;
    #pragma unroll
    for (int t = 0; t < 4; t++) out[base + t * 256] = z;
    if (blockIdx.x == 0 && threadIdx.x < EEXP) g_counts[threadIdx.x] = 0;
}

// ---------------------------------------------------------------------------
// x -> fp16 hi + scaled residual lo
// ---------------------------------------------------------------------------
__global__ __launch_bounds__(256) void convx_kernel(const float4* __restrict__ in,
                                                    __half2* __restrict__ hi,
                                                    __half2* __restrict__ lo)
{
    int i = blockIdx.x * 256 + threadIdx.x;
    float4 v = in[i];
    __half hx = __float2half_rn(v.x), hy = __float2half_rn(v.y);
    __half hz = __float2half_rn(v.z), hw = __float2half_rn(v.w);
    hi[2 * i]     = __halves2half2(hx, hy);
    hi[2 * i + 1] = __halves2half2(hz, hw);
    lo[2 * i]     = __floats2half2_rn((v.x - __half2float(hx)) * 2048.f,
                                      (v.y - __half2float(hy)) * 2048.f);
    lo[2 * i + 1] = __floats2half2_rn((v.z - __half2float(hz)) * 2048.f,
                                      (v.w - __half2float(hw)) * 2048.f);
}

// ---------------------------------------------------------------------------
// Gating weight prep: Wc[j][d] = (j<16 ? w_gate[d][j] : w_noise[d][j-16]),
// split into hi + scaled lo.
// ---------------------------------------------------------------------------
__global__ __launch_bounds__(256) void prep_gw_kernel(const float* __restrict__ wg,
                                                      const float* __restrict__ wn)
{
    int idx = blockIdx.x * 256 + threadIdx.x;   // 0..16383
    int j = idx >> 9, d = idx & 511;
    float v = (j < 16) ? wg[d * 16 + j] : wn[d * 16 + (j - 16)];
    __half h = __float2half_rn(v);
    g_WcHi[j * 512 + d] = h;
    g_WcLo[j * 512 + d] = __float2half_rn((v - __half2float(h)) * 2048.f);
}

// ---------------------------------------------------------------------------
// Transpose + fp16: dst[e][c][r] = half(src[e][r][c])
// ---------------------------------------------------------------------------
__global__ void transposeh_kernel(const float* __restrict__ src, __half* __restrict__ dst,
                                  int R, int C)
{
    __shared__ float t[32][33];
    int e = blockIdx.z;
    const float* s = src + (size_t)e * R * C;
    __half* d = dst + (size_t)e * R * C;
    int c0 = blockIdx.x * 32, r0 = blockIdx.y * 32;
    int tx = threadIdx.x, ty = threadIdx.y;
    #pragma unroll
    for (int i = 0; i < 32; i += 8)
        t[ty + i][tx] = s[(size_t)(r0 + ty + i) * C + c0 + tx];
    __syncthreads();
    #pragma unroll
    for (int i = 0; i < 32; i += 8)
        d[(size_t)(c0 + ty + i) * R + r0 + tx] = __float2half_rn(t[tx][ty + i]);
}

// ---------------------------------------------------------------------------
// Gating v7: split-fp16 tensor-core GEMM C[128,32] = x @ [w_gate|w_noise],
// error-compensated (C = hi*hi + (hi*lo + lo*hi)/2048; logit err ~1e-6).
// 256 thr / 8 warps (4m x 2n, warp tile 32x16). B resident, A double-buffered.
// Epilogue: fp32-exact softmax/threshold/renorm per row + block-aggregated
// compaction into g_rows/g_counts.
// ---------------------------------------------------------------------------
#define GB_HI   0               // 32*520*2 = 33280
#define GB_LO   33280
#define GA_HI0  66560           // 128*40*2 = 10240 each
#define GA_HI1  76800
#define GA_LO0  87040
#define GA_LO1  97280
#define G_SC    66560           // overlay after GEMM: 128*34*4 = 17408
#define G_LIST  83968           // 16*128 ints = 8192
#define G_CNT   92160           // 16 ints
#define G_BASE  92224           // 16 ints
#define G2_SMEM 107520

#define GLB  40                 // A tile stride (halves)
#define GLW  520                // B tile stride (halves)
#define INV2048 4.8828125e-4f

__global__ __launch_bounds__(256) void gating_kernel(const float* __restrict__ noise)
{
    extern __shared__ char gsm[];
    const int tid  = threadIdx.x;
    const int wid  = tid >> 5;
    const int lane = tid & 31;
    const int g    = lane >> 2;
    const int tig  = lane & 3;
    const int m0   = blockIdx.x * 128;
    const uint32_t sb = smem_u32_of(gsm);

    const int wm = wid >> 1;    // 0..3 : rows 32*wm
    const int wn = wid & 1;     // 0..1 : cols 16*wn

    // ldmatrix lane byte offsets
    const uint32_t offA  = (uint32_t)((lane & 15) * (GLB * 2) + (lane >> 4) * 16);
    const uint32_t offBG = (uint32_t)(((lane & 7) + ((lane >> 4) & 1) * 8) * (GLW * 2) + ((lane >> 3) & 1) * 16);

    // B (hi & lo) resident load: 32 rows x 512 halves each
    #pragma unroll
    for (int t = 0; t < 8; t++) {
        int id = tid + t * 256;          // 0..2047
        int r = id >> 6, q = id & 63;
        cp16(sb + GB_HI + (uint32_t)(r * (GLW * 2) + q * 16), g_WcHi + r * 512 + q * 8);
        cp16(sb + GB_LO + (uint32_t)(r * (GLW * 2) + q * 16), g_WcLo + r * 512 + q * 8);
    }

    auto loadA = [&](int c, int buf) {
        uint32_t hB = sb + (buf ? GA_HI1 : GA_HI0);
        uint32_t lB = sb + (buf ? GA_LO1 : GA_LO0);
        #pragma unroll
        for (int t = 0; t < 2; t++) {
            int id = tid + t * 256;      // 0..511
            int r = id >> 2, q = id & 3;
            cp16(hB + (uint32_t)(r * (GLB * 2) + q * 16),
                 g_Xh  + (size_t)(m0 + r) * DDIM + c * 32 + q * 8);
            cp16(lB + (uint32_t)(r * (GLB * 2) + q * 16),
                 g_Xlo + (size_t)(m0 + r) * DDIM + c * 32 + q * 8);
        }
    };

    loadA(0, 0);
    CP_COMMIT();     // B + chunk0 as one group

    float acc[2][2][4], accC[2][2][4];
    #pragma unroll
    for (int i = 0; i < 2; i++)
        #pragma unroll
        for (int j = 0; j < 2; j++)
            #pragma unroll
            for (int q = 0; q < 4; q++) { acc[i][j][q] = 0.f; accC[i][j][q] = 0.f; }

    for (int c = 0; c < 16; c++) {
        int buf = c & 1;
        CP_WAIT(0);
        __syncthreads();
        if (c + 1 < 16) { loadA(c + 1, buf ^ 1); CP_COMMIT(); }

        uint32_t aH = sb + (buf ? GA_HI1 : GA_HI0);
        uint32_t aL = sb + (buf ? GA_LO1 : GA_LO0);

        #pragma unroll
        for (int ks = 0; ks < 32; ks += 16) {
            int kg = c * 32 + ks;
            uint32_t ah[2][4], al[2][4];
            #pragma unroll
            for (int mi = 0; mi < 2; mi++) {
                uint32_t o = (uint32_t)(((wm * 32 + mi * 16) * GLB + ks) * 2);
                LDMX4(ah[mi][0], ah[mi][1], ah[mi][2], ah[mi][3], aH + o + offA);
                LDMX4(al[mi][0], al[mi][1], al[mi][2], al[mi][3], aL + o + offA);
            }
            uint32_t bh[4], bl[4];
            uint32_t ob = (uint32_t)(((wn * 16) * GLW + kg) * 2) + offBG;
            LDMX4(bh[0], bh[1], bh[2], bh[3], sb + GB_HI + ob);
            LDMX4(bl[0], bl[1], bl[2], bl[3], sb + GB_LO + ob);
            #pragma unroll
            for (int mi = 0; mi < 2; mi++) {
                mma_f16(acc [mi][0], ah[mi], bh);
                mma_f16(acc [mi][1], ah[mi], bh + 2);
                mma_f16(accC[mi][0], ah[mi], bl);
                mma_f16(accC[mi][1], ah[mi], bl + 2);
                mma_f16(accC[mi][0], al[mi], bh);
                mma_f16(accC[mi][1], al[mi], bh + 2);
            }
        }
    }
    __syncthreads();   // all A reads done; overlay region now reusable

    // ---- C -> SMEM (fp32), combine compensation term ----
    float* sC    = (float*)(gsm + G_SC);     // [128][34]
    int*   sList = (int*)(gsm + G_LIST);
    int*   sCnt  = (int*)(gsm + G_CNT);
    int*   sBase = (int*)(gsm + G_BASE);

    #pragma unroll
    for (int mi = 0; mi < 2; mi++) {
        int r0 = wm * 32 + mi * 16 + g;
        #pragma unroll
        for (int nb = 0; nb < 2; nb++) {
            int cc = wn * 16 + nb * 8 + 2 * tig;
            float2 v0, v1;
            v0.x = acc[mi][nb][0] + accC[mi][nb][0] * INV2048;
            v0.y = acc[mi][nb][1] + accC[mi][nb][1] * INV2048;
            v1.x = acc[mi][nb][2] + accC[mi][nb][2] * INV2048;
            v1.y = acc[mi][nb][3] + accC[mi][nb][3] * INV2048;
            *(float2*)&sC[r0 * 34 + cc]       = v0;
            *(float2*)&sC[(r0 + 8) * 34 + cc] = v1;
        }
    }
    if (tid < EEXP) sCnt[tid] = 0;
    __syncthreads();

    // ---- per-row fp32-exact softmax / threshold / renorm + local compaction ----
    if (tid < 128) {
        int r = m0 + tid;
        float lg[16], p[16];
        float mx = -1e30f;
        #pragma unroll
        for (int j = 0; j < 16; j++) {
            float cl = sC[tid * 34 + j];
            float sd = softplusf(sC[tid * 34 + 16 + j]) + 0.01f;
            lg[j] = fmaf(noise[(size_t)r * EEXP + j], sd, cl);
            mx = fmaxf(mx, lg[j]);
        }
        float s = 0.f;
        #pragma unroll
        for (int j = 0; j < 16; j++) { p[j] = expf(lg[j] - mx); s += p[j]; }
        float s2 = 0.f;
        #pragma unroll
        for (int j = 0; j < 16; j++) { p[j] = p[j] / s; s2 += p[j]; }
        float meanw = s2 * (1.f / 16.f) - 1e-8f;
        float gs = 0.f;
        #pragma unroll
        for (int j = 0; j < 16; j++) {
            p[j] = (p[j] >= meanw) ? p[j] : 0.f;
            gs += p[j];
        }
        #pragma unroll
        for (int j = 0; j < 16; j++) {
            g_gates[(size_t)r * EEXP + j] = p[j] / gs;
            if (p[j] > 0.f) {
                int idx = atomicAdd(&sCnt[j], 1);
                sList[j * 128 + idx] = r;
            }
        }
    }
    __syncthreads();

    if (tid < EEXP) sBase[tid] = atomicAdd(&g_counts[tid], sCnt[tid]);
    __syncthreads();

    for (int j = 0; j < EEXP; j++) {
        int n = sCnt[j], b = sBase[j];
        for (int i = tid; i < n; i += 256)
            g_rows[j * B_ROWS + b + i] = sList[j * 128 + i];
    }
}

// ---------------------------------------------------------------------------
// Fused expert MLP v7 (unchanged from R11): sparse row dispatch, fp16 mma,
// 3-stage cp.async pipeline, resident W2, barrier-free phase 2.
// ---------------------------------------------------------------------------
#define SM_H     0              // 128*264*2 = 67584
#define SM_A0    67584          // 128*40*2  = 10240 (x3)
#define SM_B0    98304          // 256*40*2  = 20480 (x3)
#define SM_W2    159744         // 64*264*2  = 33792
#define SM_BIAS  193536         // 256f + 64f = 1280
#define SM_ROWS  194816         // 128 ints = 512
#define SMEM_MOE 195328

#define LDK1 40   // phase-1 tile stride (halves)
#define LDH  264  // h tile stride (halves)
#define LDW2 264  // W2 tile stride (halves)

__global__ __launch_bounds__(512, 1) void moe_kernel(
    const float* __restrict__ b1, const float* __restrict__ b2,
    float* __restrict__ out)
{
    extern __shared__ char smem[];
    __half* sH    = (__half*)(smem + SM_H);
    float* sBias1 = (float*)(smem + SM_BIAS);
    float* sBias2 = sBias1 + HDIM;
    int*   sRows  = (int*)(smem + SM_ROWS);

    const int e   = blockIdx.y;
    const int m0  = blockIdx.x * 128;
    const int cnt = g_counts[e];
    if (m0 >= cnt) return;

    const int tid  = threadIdx.x;
    const int wid  = tid >> 5;
    const int lane = tid & 31;
    const int g    = lane >> 2;
    const int tig  = lane & 3;

    const uint32_t smem_b = smem_u32_of(smem);

    const __half* w1e = g_W1T + (size_t)e * HDIM * DDIM;
    const __half* w2e = g_W2T + (size_t)e * LOUT * HDIM;

    if (tid < 128) {
        int p = m0 + tid;
        sRows[tid] = g_rows[e * B_ROWS + (p < cnt ? p : cnt - 1)];
    }
    if (tid < HDIM) sBias1[tid] = b1[(size_t)e * HDIM + tid];
    if (tid < LOUT) sBias2[tid] = b2[(size_t)e * LOUT + tid];
    __syncthreads();   // sRows visible before gathered cp.async

    const uint32_t offA  = (uint32_t)((lane & 15) * (LDK1 * 2) + (lane >> 4) * 16);
    const uint32_t offB  = (uint32_t)(((lane & 7) + ((lane >> 4) & 1) * 8) * (LDK1 * 2) + ((lane >> 3) & 1) * 16);
    const uint32_t offA2 = (uint32_t)((lane & 15) * (LDH * 2) + (lane >> 4) * 16);
    const uint32_t offB2 = (uint32_t)(((lane & 7) + ((lane >> 4) & 1) * 8) * (LDW2 * 2) + ((lane >> 3) & 1) * 16);

    const int wm = wid >> 2;
    const int wn = wid & 3;

    float acc[2][8][4];
    #pragma unroll
    for (int i = 0; i < 2; i++)
        #pragma unroll
        for (int j = 0; j < 8; j++)
            #pragma unroll
            for (int q = 0; q < 4; q++) acc[i][j][q] = 0.f;

    auto load_chunk1 = [&](int c, int buf) {
        uint32_t aBase = smem_b + SM_A0 + buf * 10240;
        uint32_t bBase = smem_b + SM_B0 + buf * 20480;
        {
            int r = tid >> 2, q = tid & 3;
            const __half* src = g_Xh + (size_t)sRows[r] * DDIM + c * 32 + q * 8;
            cp16(aBase + (uint32_t)(r * (LDK1 * 2) + q * 16), src);
        }
        #pragma unroll
        for (int t = 0; t < 2; t++) {
            int id = tid + t * 512;
            int r = id >> 2, q = id & 3;
            cp16(bBase + (uint32_t)(r * (LDK1 * 2) + q * 16),
                 w1e + (size_t)r * DDIM + c * 32 + q * 8);
        }
        CP_COMMIT();
    };

    load_chunk1(0, 0);
    load_chunk1(1, 1);

    for (int c = 0; c < 16; c++) {
        int buf = c % 3;
        CP_WAIT(1);
        __syncthreads();
        if (c + 2 < 16) {
            load_chunk1(c + 2, (c + 2) % 3);
        } else if (c + 2 == 16) {
            uint32_t wBase = smem_b + SM_W2;
            #pragma unroll
            for (int t = 0; t < 4; t++) {
                int id = tid + t * 512;
                int r = id >> 5, q = id & 31;
                cp16(wBase + (uint32_t)(r * (LDW2 * 2) + q * 16),
                     w2e + (size_t)r * HDIM + q * 8);
            }
            CP_COMMIT();
        }

        const uint32_t aB = smem_b + SM_A0 + buf * 10240;
        const uint32_t bB = smem_b + SM_B0 + buf * 20480;

        #pragma unroll
        for (int ks = 0; ks < 32; ks += 16) {
            uint32_t af[2][4];
            #pragma unroll
            for (int i = 0; i < 2; i++) {
                uint32_t ad = aB + (uint32_t)(((wm * 32 + i * 16) * LDK1 + ks) * 2) + offA;
                LDMX4(af[i][0], af[i][1], af[i][2], af[i][3], ad);
            }
            uint32_t bf[8][2];
            #pragma unroll
            for (int j2 = 0; j2 < 4; j2++) {
                uint32_t bd = bB + (uint32_t)(((wn * 64 + j2 * 16) * LDK1 + ks) * 2) + offB;
                LDMX4(bf[2 * j2][0], bf[2 * j2][1], bf[2 * j2 + 1][0], bf[2 * j2 + 1][1], bd);
            }
            #pragma unroll
            for (int i = 0; i < 2; i++)
                #pragma unroll
                for (int j = 0; j < 8; j++)
                    mma_f16(acc[i][j], af[i], bf[j]);
        }
    }

    // ---- tanh(C1 + b1) -> sH (fp16) ----
    #pragma unroll
    for (int i = 0; i < 2; i++) {
        int r0 = wm * 32 + i * 16 + g;
        #pragma unroll
        for (int j = 0; j < 8; j++) {
            int cc = wn * 64 + j * 8 + 2 * tig;
            float bb0 = sBias1[cc], bb1 = sBias1[cc + 1];
            *(__half2*)&sH[r0 * LDH + cc] =
                __floats2half2_rn(tanh_fast(acc[i][j][0] + bb0), tanh_fast(acc[i][j][1] + bb1));
            *(__half2*)&sH[(r0 + 8) * LDH + cc] =
                __floats2half2_rn(tanh_fast(acc[i][j][2] + bb0), tanh_fast(acc[i][j][3] + bb1));
        }
    }
    CP_WAIT(0);
    __syncthreads();

    // ---- phase 2: 32x16 warp tiles, K=256, barrier-free ----
    const int wm2 = wid >> 2;
    const int wn2 = wid & 3;

    float acc2[2][2][4];
    #pragma unroll
    for (int i = 0; i < 2; i++)
        #pragma unroll
        for (int j = 0; j < 2; j++)
            #pragma unroll
            for (int q = 0; q < 4; q++) acc2[i][j][q] = 0.f;

    const uint32_t hB = smem_b + SM_H;
    const uint32_t wB = smem_b + SM_W2;

    #pragma unroll
    for (int ks = 0; ks < 256; ks += 16) {
        uint32_t af[2][4];
        #pragma unroll
        for (int i = 0; i < 2; i++) {
            uint32_t ad = hB + (uint32_t)(((wm2 * 32 + i * 16) * LDH + ks) * 2) + offA2;
            LDMX4(af[i][0], af[i][1], af[i][2], af[i][3], ad);
        }
        uint32_t bf[4];
        uint32_t bd = wB + (uint32_t)(((wn2 * 16) * LDW2 + ks) * 2) + offB2;
        LDMX4(bf[0], bf[1], bf[2], bf[3], bd);
        #pragma unroll
        for (int i = 0; i < 2; i++) {
            mma_f16(acc2[i][0], af[i], bf);
            mma_f16(acc2[i][1], af[i], bf + 2);
        }
    }

    // ---- epilogue: scatter out[row, e] = gate * (C2 + b2) ----
    #pragma unroll
    for (int i = 0; i < 2; i++) {
        int p0 = wm2 * 32 + i * 16 + g;
        #pragma unroll
        for (int h = 0; h < 2; h++) {
            int p = p0 + h * 8;
            if (m0 + p < cnt) {
                int row = sRows[p];
                float gate = g_gates[(size_t)row * EEXP + e];
                float* op = out + ((size_t)row * EEXP + e) * LOUT;
                #pragma unroll
                for (int j = 0; j < 2; j++) {
                    int cc = wn2 * 16 + j * 8 + 2 * tig;
                    float2 o;
                    o.x = (acc2[i][j][2 * h + 0] + sBias2[cc])     * gate;
                    o.y = (acc2[i][j][2 * h + 1] + sBias2[cc + 1]) * gate;
                    *(float2*)(op + cc) = o;
                }
            }
        }
    }
}

// ---------------------------------------------------------------------------
extern "C" void kernel_launch(void* const* d_in, const int* in_sizes, int n_in,
                              void* d_out, int out_size)
{
    const float* x       = (const float*)d_in[0];
    const float* noise   = (const float*)d_in[1];
    const float* w_gate  = (const float*)d_in[2];
    const float* w_noise = (const float*)d_in[3];
    const float* W1      = (const float*)d_in[4];
    const float* b1      = (const float*)d_in[5];
    const float* W2      = (const float*)d_in[6];
    const float* b2      = (const float*)d_in[7];
    float* out = (float*)d_out;

    __half* xh;  cudaGetSymbolAddress((void**)&xh,  g_Xh);
    __half* xlo; cudaGetSymbolAddress((void**)&xlo, g_Xlo);
    __half* w1t; cudaGetSymbolAddress((void**)&w1t, g_W1T);
    __half* w2t; cudaGetSymbolAddress((void**)&w2t, g_W2T);

    cudaFuncSetAttribute(gating_kernel, cudaFuncAttributeMaxDynamicSharedMemorySize, G2_SMEM);
    cudaFuncSetAttribute(moe_kernel,    cudaFuncAttributeMaxDynamicSharedMemorySize, SMEM_MOE);

    zerofill_kernel<<<B_ROWS * EEXP * LOUT / 4 / 1024, 256>>>((float4*)out);
    convx_kernel<<<B_ROWS * DDIM / 4 / 256, 256>>>((const float4*)x, (__half2*)xh, (__half2*)xlo);
    prep_gw_kernel<<<64, 256>>>(w_gate, w_noise);
    transposeh_kernel<<<dim3(HDIM / 32, DDIM / 32, EEXP), dim3(32, 8)>>>(W1, w1t, DDIM, HDIM);
    transposeh_kernel<<<dim3(LOUT / 32, HDIM / 32, EEXP), dim3(32, 8)>>>(W2, w2t, HDIM, LOUT);
    gating_kernel<<<B_ROWS / 128, 256, G2_SMEM>>>(noise);
    moe_kernel<<<dim3(B_ROWS / 128, EEXP), 512, SMEM_MOE>>>(b1, b2, out);
}